// round 8
// baseline (speedup 1.0000x reference)
#include <cuda_runtime.h>

// Problem dims (fixed by the reference)
#define Gn   32
#define NN   4000
#define EE   32000
#define FD0  64
#define HD   128
#define BNR  16000
#define STEPS 8

typedef unsigned long long u64;

__device__ __forceinline__ u64 fma2(u64 a, u64 b, u64 c) {
    u64 d;
    asm("fma.rn.f32x2 %0, %1, %2, %3;" : "=l"(d) : "l"(a), "l"(b), "l"(c));
    return d;
}
__device__ __forceinline__ u64 pack2(float x) {
    u64 d; asm("mov.b64 %0, {%1, %1};" : "=l"(d) : "f"(x)); return d;
}

// ---------------- scratch (device globals) --------------------------------------
__device__ float d_deg_out[Gn * NN];
__device__ float d_deg_in [Gn * NN];
__device__ int   d_cnt_f[Gn * NN];
__device__ int   d_cnt_b[Gn * NN];
__device__ int   d_off_f[Gn * NN];
__device__ int   d_off_b[Gn * NN];
__device__ int   d_cur_f[Gn * NN];
__device__ int   d_cur_b[Gn * NN];
__device__ int   d_csr_if[Gn * EE];
__device__ float d_csr_wf[Gn * EE];
__device__ int   d_csr_ib[Gn * EE];
__device__ float d_csr_wb[Gn * EE];
__device__ float d_aggf  [(size_t)Gn * NN * HD];
__device__ float d_aggb  [(size_t)Gn * NN * HD];
__device__ float d_h0    [(size_t)Gn * NN * HD];
__device__ float d_h1    [(size_t)Gn * NN * HD];
__device__ float d_gx    [(size_t)BNR * STEPS * 4 * HD];
__device__ float d_whhT  [HD * 4 * HD];   // Whh^T [128][512]
__device__ float d_wpT   [HD * FD0];      // Wp^T  [128][64]

// ---------------- CSR build ------------------------------------------------------
__global__ void zero_kernel() {
    int i = blockIdx.x * blockDim.x + threadIdx.x;
    if (i < Gn * NN) {
        d_deg_out[i] = 0.f; d_deg_in[i] = 0.f;
        d_cnt_f[i] = 0;     d_cnt_b[i] = 0;
    }
}

__global__ void degcnt_kernel(const int* __restrict__ ei, const float* __restrict__ ew) {
    int i = blockIdx.x * blockDim.x + threadIdx.x;
    if (i >= Gn * EE) return;
    int g = i / EE, e = i - g * EE;
    const int* eig = ei + (size_t)g * 2 * EE;
    int src = eig[e], dst = eig[EE + e];
    float w = ew[i];
    atomicAdd(&d_deg_out[g * NN + src], w);
    atomicAdd(&d_deg_in [g * NN + dst], w);
    atomicAdd(&d_cnt_f[g * NN + dst], 1);
    atomicAdd(&d_cnt_b[g * NN + src], 1);
}

__global__ void inv_kernel() {
    int i = blockIdx.x * blockDim.x + threadIdx.x;
    if (i >= Gn * NN) return;
    float v = d_deg_out[i];
    d_deg_out[i] = (v > 0.f) ? rsqrtf(fmaxf(v, 1e-12f)) : 0.f;
    v = d_deg_in[i];
    d_deg_in[i]  = (v > 0.f) ? rsqrtf(fmaxf(v, 1e-12f)) : 0.f;
}

__global__ void __launch_bounds__(1024) scan_kernel() {
    int g   = blockIdx.x;
    int dir = blockIdx.y;
    const int* cnt = dir ? d_cnt_b : d_cnt_f;
    int* off = dir ? d_off_b : d_off_f;
    int* cur = dir ? d_cur_b : d_cur_f;
    int tid = threadIdx.x;
    int base = g * NN;
    int v[4], tot = 0;
#pragma unroll
    for (int k = 0; k < 4; k++) {
        int i = tid * 4 + k;
        v[k] = (i < NN) ? cnt[base + i] : 0;
        tot += v[k];
    }
    __shared__ int s[1024];
    s[tid] = tot;
    __syncthreads();
    for (int d = 1; d < 1024; d <<= 1) {
        int t = (tid >= d) ? s[tid - d] : 0;
        __syncthreads();
        s[tid] += t;
        __syncthreads();
    }
    int ex = s[tid] - tot;
#pragma unroll
    for (int k = 0; k < 4; k++) {
        int i = tid * 4 + k;
        if (i < NN) { off[base + i] = ex; cur[base + i] = ex; ex += v[k]; }
    }
}

__global__ void scatter_kernel(const int* __restrict__ ei, const float* __restrict__ ew) {
    int i = blockIdx.x * blockDim.x + threadIdx.x;
    if (i >= Gn * EE) return;
    int g = i / EE, e = i - g * EE;
    const int* eig = ei + (size_t)g * 2 * EE;
    int src = eig[e], dst = eig[EE + e];
    float w = ew[i] * d_deg_out[g * NN + src] * d_deg_in[g * NN + dst];
    int pf = atomicAdd(&d_cur_f[g * NN + dst], 1);
    d_csr_if[g * EE + pf] = src;
    d_csr_wf[g * EE + pf] = w;
    int pb = atomicAdd(&d_cur_b[g * NN + src], 1);
    d_csr_ib[g * EE + pb] = dst;
    d_csr_wb[g * EE + pb] = w;
}

// ---------------- gather aggregation: one warp per (node, dir) -------------------
template<int FD>
__global__ void __launch_bounds__(256) gather_kernel(const float* __restrict__ x) {
    int gw = (blockIdx.x * 256 + threadIdx.x) >> 5;
    int lane = threadIdx.x & 31;
    if (gw >= Gn * NN * 2) return;
    int dir = gw & 1;
    int gn  = gw >> 1;
    int g   = gn / NN;
    const int*   off = dir ? d_off_b : d_off_f;
    const int*   cnt = dir ? d_cnt_b : d_cnt_f;
    const int*   nb  = dir ? d_csr_ib : d_csr_if;
    const float* wv  = dir ? d_csr_wb : d_csr_wf;
    float* outp      = dir ? d_aggb   : d_aggf;
    int o = off[gn], c = cnt[gn];
    const float* xg = x + (size_t)g * NN * FD;
    const int ebase = g * EE + o;

    if (FD == 128) {
        float4 acc = make_float4(0.f, 0.f, 0.f, 0.f);
        for (int j = 0; j < c; j++) {
            int   s = nb[ebase + j];
            float w = wv[ebase + j];
            float4 xv = *(const float4*)(xg + (size_t)s * FD + lane * 4);
            acc.x += w * xv.x; acc.y += w * xv.y;
            acc.z += w * xv.z; acc.w += w * xv.w;
        }
        *(float4*)(outp + (size_t)gn * FD + lane * 4) = acc;
    } else {
        float2 acc = make_float2(0.f, 0.f);
        for (int j = 0; j < c; j++) {
            int   s = nb[ebase + j];
            float w = wv[ebase + j];
            float2 xv = *(const float2*)(xg + (size_t)s * FD + lane * 2);
            acc.x += w * xv.x; acc.y += w * xv.y;
        }
        *(float2*)(outp + (size_t)gn * FD + lane * 2) = acc;
    }
}

// ---------------- FMA2 GEMM: 128x128 tile, row-pair accumulators, dup-W smem ----
// Thread (ty,tx): rows ty*8..+7 (as 4 u64 row-pairs), cols {tx*4..+3, 64+tx*4..+3}.
// Inner loop has NO pack2: A pairs come from contiguous As rows; W pairs from
// value-duplicated Wd staging. Ordering matches round-5 winner: sync;stage;sync;compute.
template<int KD, bool DUAL>
__global__ void __launch_bounds__(256)
gemm2_kernel(const float* __restrict__ A0, const float* __restrict__ A1,
             const float* __restrict__ W0, const float* __restrict__ W1,
             const float* __restrict__ b0, const float* __restrict__ b1,
             float* __restrict__ C, int M, int NC,
             float s0, float s1, float bs0, float bs1)
{
    __shared__ float As[16][132];
    __shared__ float Wd[16][264];     // duplicated: Wd[k][2j] = Wd[k][2j+1] = W[j][k]*s
    const int tid = threadIdx.x;
    const int m0  = blockIdx.x * 128;
    const int jn  = blockIdx.y * 128;
    const int ty  = tid >> 4;
    const int tx  = tid & 15;

    u64 acc[4][8];   // [rowpair][col]; lo = row ty*8+2rp, hi = row ty*8+2rp+1
#pragma unroll
    for (int rp = 0; rp < 4; rp++)
#pragma unroll
        for (int cc = 0; cc < 8; cc++) acc[rp][cc] = 0ull;

    const int npass = DUAL ? 2 : 1;
    for (int pass = 0; pass < npass; pass++) {
        const float* A = pass ? A1 : A0;
        const float* W = pass ? W1 : W0;
        const float  s = pass ? s1 : s0;
        for (int kt = 0; kt < KD; kt += 16) {
            __syncthreads();
#pragma unroll
            for (int half = 0; half < 2; half++) {   // stage A tile transposed
                int r  = (tid >> 2) + half * 64;
                int k4 = (tid & 3) << 2;
                float4 v = *(const float4*)(A + (size_t)(m0 + r) * KD + kt + k4);
                As[k4 + 0][r] = v.x; As[k4 + 1][r] = v.y;
                As[k4 + 2][r] = v.z; As[k4 + 3][r] = v.w;
            }
#pragma unroll
            for (int half = 0; half < 2; half++) {   // stage W duplicated+scaled
                int j  = (tid >> 2) + half * 64;
                int k4 = (tid & 3) << 2;
                float4 v = *(const float4*)(W + (size_t)(jn + j) * KD + kt + k4);
                Wd[k4 + 0][2 * j] = v.x * s; Wd[k4 + 0][2 * j + 1] = v.x * s;
                Wd[k4 + 1][2 * j] = v.y * s; Wd[k4 + 1][2 * j + 1] = v.y * s;
                Wd[k4 + 2][2 * j] = v.z * s; Wd[k4 + 2][2 * j + 1] = v.z * s;
                Wd[k4 + 3][2 * j] = v.w * s; Wd[k4 + 3][2 * j + 1] = v.w * s;
            }
            __syncthreads();
#pragma unroll
            for (int kk = 0; kk < 16; kk++) {
                float4 a0 = *(const float4*)&As[kk][ty * 8];       // rows 0..3
                float4 a1 = *(const float4*)&As[kk][ty * 8 + 4];   // rows 4..7
                u64 ap[4];
                ap[0] = *(const u64*)&a0.x;   // rows (0,1)
                ap[1] = *(const u64*)&a0.z;   // rows (2,3)
                ap[2] = *(const u64*)&a1.x;   // rows (4,5)
                ap[3] = *(const u64*)&a1.z;   // rows (6,7)
                float4 w0 = *(const float4*)&Wd[kk][8 * tx];            // cols j1, j1+1
                float4 w1 = *(const float4*)&Wd[kk][8 * tx + 4];        // cols j1+2, j1+3
                float4 w2 = *(const float4*)&Wd[kk][128 + 8 * tx];      // cols j2, j2+1
                float4 w3 = *(const float4*)&Wd[kk][128 + 8 * tx + 4];  // cols j2+2, j2+3
                u64 wd[8];
                wd[0] = *(const u64*)&w0.x; wd[1] = *(const u64*)&w0.z;
                wd[2] = *(const u64*)&w1.x; wd[3] = *(const u64*)&w1.z;
                wd[4] = *(const u64*)&w2.x; wd[5] = *(const u64*)&w2.z;
                wd[6] = *(const u64*)&w3.x; wd[7] = *(const u64*)&w3.z;
#pragma unroll
                for (int rp = 0; rp < 4; rp++)
#pragma unroll
                    for (int cc = 0; cc < 8; cc++)
                        acc[rp][cc] = fma2(ap[rp], wd[cc], acc[rp][cc]);
            }
        }
    }

    int j1 = jn + tx * 4;
    int j2 = jn + 64 + tx * 4;
    float biasA[4], biasB[4];
#pragma unroll
    for (int cidx = 0; cidx < 4; cidx++) {
        biasA[cidx] = bs0 * b0[j1 + cidx] + bs1 * b1[j1 + cidx];
        biasB[cidx] = bs0 * b0[j2 + cidx] + bs1 * b1[j2 + cidx];
    }
#pragma unroll
    for (int rp = 0; rp < 4; rp++) {
        float2 cA[8];
#pragma unroll
        for (int cc = 0; cc < 8; cc++) cA[cc] = *(float2*)&acc[rp][cc];
        int mlo = m0 + ty * 8 + 2 * rp;
        float4 lo0 = make_float4(cA[0].x + biasA[0], cA[1].x + biasA[1],
                                 cA[2].x + biasA[2], cA[3].x + biasA[3]);
        float4 lo1 = make_float4(cA[4].x + biasB[0], cA[5].x + biasB[1],
                                 cA[6].x + biasB[2], cA[7].x + biasB[3]);
        float4 hi0 = make_float4(cA[0].y + biasA[0], cA[1].y + biasA[1],
                                 cA[2].y + biasA[2], cA[3].y + biasA[3]);
        float4 hi1 = make_float4(cA[4].y + biasB[0], cA[5].y + biasB[1],
                                 cA[6].y + biasB[2], cA[7].y + biasB[3]);
        *(float4*)(C + (size_t)mlo * NC + j1)       = lo0;
        *(float4*)(C + (size_t)mlo * NC + j2)       = lo1;
        *(float4*)(C + (size_t)(mlo + 1) * NC + j1) = hi0;
        *(float4*)(C + (size_t)(mlo + 1) * NC + j2) = hi1;
    }
}

// ---------------- prep: Whh^T and Wp^T -------------------------------------------
__global__ void prep_kernel(const float* __restrict__ Whh, const float* __restrict__ Wp) {
    int i = blockIdx.x * blockDim.x + threadIdx.x;
    if (i < 512 * 128) {
        int j = i >> 7, k = i & 127;
        d_whhT[(size_t)k * 512 + j] = Whh[i];
    }
    if (i < 64 * 128) {
        int j = i >> 7, k = i & 127;
        d_wpT[k * 64 + j] = Wp[i];
    }
}

// ---------------- LSTM recurrence + fused projection ----------------------------
__device__ __forceinline__ float sigmoidf_(float x) { return 1.f / (1.f + __expf(-x)); }

__global__ void __launch_bounds__(256)
lstm_kernel(float* __restrict__ out, const float* __restrict__ bp)
{
    __shared__ float h_s[32][128];
    __shared__ float w_s[16][512];     // reused as Wp^T [128][64] in epilogue
    const int tid  = threadIdx.x;
    const int tc   = tid & 31;
    const int tr   = tid >> 5;
    const int row0 = blockIdx.x * 32 + tr * 4;

    float c[4][4];
#pragma unroll
    for (int a = 0; a < 4; a++)
#pragma unroll
        for (int b = 0; b < 4; b++) c[a][b] = 0.f;

    for (int t = 0; t < STEPS; t++) {
        u64 acc[4][4][2];   // [gate][row][colpair]
#pragma unroll
        for (int gate = 0; gate < 4; gate++)
#pragma unroll
            for (int ri = 0; ri < 4; ri++) {
                float4 v = *(const float4*)(d_gx +
                    ((size_t)(row0 + ri) * STEPS + t) * 512 + gate * 128 + tc * 4);
                acc[gate][ri][0] = *(const u64*)&v.x;
                acc[gate][ri][1] = *(const u64*)&v.z;
            }

        if (t > 0) {
            for (int kt = 0; kt < 8; kt++) {
                __syncthreads();
#pragma unroll
                for (int i = 0; i < 8; i++) {
                    int q  = tid + i * 256;
                    int kk = q >> 7;
                    int j4 = (q & 127) << 2;
                    *(float4*)&w_s[kk][j4] =
                        *(const float4*)(d_whhT + (size_t)(kt * 16 + kk) * 512 + j4);
                }
                __syncthreads();
#pragma unroll
                for (int kk = 0; kk < 16; kk++) {
                    u64 hp[4];
#pragma unroll
                    for (int ri = 0; ri < 4; ri++)
                        hp[ri] = pack2(h_s[tr * 4 + ri][kt * 16 + kk]);
#pragma unroll
                    for (int gate = 0; gate < 4; gate++) {
                        float4 w = *(const float4*)&w_s[kk][gate * 128 + tc * 4];
                        u64 w01 = *(const u64*)&w.x;
                        u64 w23 = *(const u64*)&w.z;
#pragma unroll
                        for (int ri = 0; ri < 4; ri++) {
                            acc[gate][ri][0] = fma2(hp[ri], w01, acc[gate][ri][0]);
                            acc[gate][ri][1] = fma2(hp[ri], w23, acc[gate][ri][1]);
                        }
                    }
                }
            }
            __syncthreads();
        }

#pragma unroll
        for (int ri = 0; ri < 4; ri++) {
            float2 i01 = *(float2*)&acc[0][ri][0], i23 = *(float2*)&acc[0][ri][1];
            float2 f01 = *(float2*)&acc[1][ri][0], f23 = *(float2*)&acc[1][ri][1];
            float2 g01 = *(float2*)&acc[2][ri][0], g23 = *(float2*)&acc[2][ri][1];
            float2 o01 = *(float2*)&acc[3][ri][0], o23 = *(float2*)&acc[3][ri][1];
            float ig[4] = {i01.x, i01.y, i23.x, i23.y};
            float fg[4] = {f01.x, f01.y, f23.x, f23.y};
            float gg[4] = {g01.x, g01.y, g23.x, g23.y};
            float og[4] = {o01.x, o01.y, o23.x, o23.y};
            float hn[4];
#pragma unroll
            for (int ci = 0; ci < 4; ci++) {
                float iv = sigmoidf_(ig[ci]);
                float fv = sigmoidf_(fg[ci]);
                float gv = tanhf(gg[ci]);
                float ov = sigmoidf_(og[ci]);
                float cn = fv * c[ri][ci] + iv * gv;
                c[ri][ci] = cn;
                hn[ci] = ov * tanhf(cn);
            }
            *(float4*)&h_s[tr * 4 + ri][tc * 4] = make_float4(hn[0], hn[1], hn[2], hn[3]);
        }
        __syncthreads();
    }

    // ---- fused projection: out[orow][0..63] = h_s[prow] @ Wp^T + bp ----
    float* wp = &w_s[0][0];   // reuse as [128][64]
#pragma unroll
    for (int i = 0; i < 8; i++) {
        int q = tid + i * 256;             // 2048 float4 chunks
        *(float4*)&wp[q * 4] = *(const float4*)(d_wpT + q * 4);
    }
    __syncthreads();

    const int prow = tid >> 3;             // 0..31
    const int cg   = tid & 7;              // cols cg*8..+7
    const int orow = blockIdx.x * 32 + prow;
    u64 pacc[4] = {0ull, 0ull, 0ull, 0ull};
#pragma unroll 8
    for (int k = 0; k < 128; k++) {
        u64 hv = pack2(h_s[prow][k]);
        float4 wa = *(const float4*)&wp[k * 64 + cg * 8];
        float4 wb = *(const float4*)&wp[k * 64 + cg * 8 + 4];
        pacc[0] = fma2(hv, *(const u64*)&wa.x, pacc[0]);
        pacc[1] = fma2(hv, *(const u64*)&wa.z, pacc[1]);
        pacc[2] = fma2(hv, *(const u64*)&wb.x, pacc[2]);
        pacc[3] = fma2(hv, *(const u64*)&wb.z, pacc[3]);
    }
    float4 bpa = *(const float4*)(bp + cg * 8);
    float4 bpb = *(const float4*)(bp + cg * 8 + 4);
    float2 q0 = *(float2*)&pacc[0];
    float2 q1 = *(float2*)&pacc[1];
    float2 q2 = *(float2*)&pacc[2];
    float2 q3 = *(float2*)&pacc[3];
    float4 o0 = make_float4(q0.x + bpa.x, q0.y + bpa.y, q1.x + bpa.z, q1.y + bpa.w);
    float4 o1 = make_float4(q2.x + bpb.x, q2.y + bpb.y, q3.x + bpb.z, q3.y + bpb.w);
    *(float4*)(out + (size_t)orow * 64 + cg * 8)     = o0;
    *(float4*)(out + (size_t)orow * 64 + cg * 8 + 4) = o1;
}

// ---------------- launch --------------------------------------------------------
extern "C" void kernel_launch(void* const* d_in, const int* in_sizes, int n_in,
                              void* d_out, int out_size)
{
    const float* x_seq = (const float*)d_in[0];
    const int*   ei    = (const int*)  d_in[1];
    const float* ew    = (const float*)d_in[2];
    const float* W0s   = (const float*)d_in[3];
    const float* b0s   = (const float*)d_in[4];
    const float* W0d   = (const float*)d_in[5];
    const float* b0d   = (const float*)d_in[6];
    const float* W1s   = (const float*)d_in[7];
    const float* b1s   = (const float*)d_in[8];
    const float* W1d   = (const float*)d_in[9];
    const float* b1d   = (const float*)d_in[10];
    const float* Wih   = (const float*)d_in[11];
    const float* Whh   = (const float*)d_in[12];
    const float* bih   = (const float*)d_in[13];
    const float* bhh   = (const float*)d_in[14];
    const float* Wp    = (const float*)d_in[15];
    const float* bp    = (const float*)d_in[16];
    float* out = (float*)d_out;

    float *aggf, *aggb, *h0, *h1, *gx;
    cudaGetSymbolAddress((void**)&aggf, d_aggf);
    cudaGetSymbolAddress((void**)&aggb, d_aggb);
    cudaGetSymbolAddress((void**)&h0,   d_h0);
    cudaGetSymbolAddress((void**)&h1,   d_h1);
    cudaGetSymbolAddress((void**)&gx,   d_gx);

    const int M = Gn * NN;   // 128000

    // ---- CSR build ----
    zero_kernel<<<(Gn * NN + 255) / 256, 256>>>();
    degcnt_kernel<<<(Gn * EE + 255) / 256, 256>>>(ei, ew);
    inv_kernel<<<(Gn * NN + 255) / 256, 256>>>();
    scan_kernel<<<dim3(Gn, 2), 1024>>>();
    scatter_kernel<<<(Gn * EE + 255) / 256, 256>>>(ei, ew);

    const int gblocks = (Gn * NN * 2 * 32 + 255) / 256;

    // ---- GCN layer 0 (F=64 -> H=128) ----
    gather_kernel<64><<<gblocks, 256>>>(x_seq);
    gemm2_kernel<64, true><<<dim3(M / 128, 1), 256>>>(
        aggf, aggb, W0s, W0d, b0s, b0d, h0, M, HD, 0.5f, 0.5f, 0.5f, 0.5f);

    // ---- GCN layer 1 (H=128 -> H=128) ----
    gather_kernel<128><<<gblocks, 256>>>(h0);
    gemm2_kernel<128, true><<<dim3(M / 128, 1), 256>>>(
        aggf, aggb, W1s, W1d, b1s, b1d, h1, M, HD, 0.5f, 0.5f, 0.5f, 0.5f);

    // ---- LSTM input GEMM: x@Wih.T + bih + bhh ----
    prep_kernel<<<256, 256>>>(Whh, Wp);
    gemm2_kernel<128, false><<<dim3(M / 128, 4), 256>>>(
        h1, nullptr, Wih, nullptr, bih, bhh, gx, M, 4 * HD, 1.f, 0.f, 1.f, 1.f);

    // ---- LSTM recurrence + fused projection ----
    lstm_kernel<<<BNR / 32, 256>>>(out, bp);
}

// round 10
// speedup vs baseline: 1.5683x; 1.5683x over previous
#include <cuda_runtime.h>
#include <cuda_bf16.h>
#include <mma.h>

using namespace nvcuda;

// Problem dims (fixed by the reference)
#define Gn   32
#define NN   4000
#define EE   32000
#define FD0  64
#define HD   128
#define BNR  16000
#define STEPS 8

typedef unsigned long long u64;

__device__ __forceinline__ u64 fma2(u64 a, u64 b, u64 c) {
    u64 d;
    asm("fma.rn.f32x2 %0, %1, %2, %3;" : "=l"(d) : "l"(a), "l"(b), "l"(c));
    return d;
}
__device__ __forceinline__ u64 pack2(float x) {
    u64 d; asm("mov.b64 %0, {%1, %1};" : "=l"(d) : "f"(x)); return d;
}

// ---------------- scratch (device globals) --------------------------------------
__device__ float d_deg_out[Gn * NN];
__device__ float d_deg_in [Gn * NN];
__device__ int   d_cnt_f[Gn * NN];
__device__ int   d_cnt_b[Gn * NN];
__device__ int   d_off_f[Gn * NN];
__device__ int   d_off_b[Gn * NN];
__device__ int   d_cur_f[Gn * NN];
__device__ int   d_cur_b[Gn * NN];
__device__ int   d_csr_if[Gn * EE];
__device__ float d_csr_wf[Gn * EE];
__device__ int   d_csr_ib[Gn * EE];
__device__ float d_csr_wb[Gn * EE];
__device__ float d_aggf  [(size_t)Gn * NN * HD];
__device__ float d_aggb  [(size_t)Gn * NN * HD];
__device__ float d_h0    [(size_t)Gn * NN * HD];
__device__ float d_h1    [(size_t)Gn * NN * HD];
__device__ float d_gx    [(size_t)BNR * STEPS * 4 * HD];
__device__ float d_whhT  [HD * 4 * HD];   // Whh^T [128][512]
__device__ float d_wpT   [HD * FD0];      // Wp^T  [128][64]
// bf16x3 tensor path (plain layouts)
__device__ __nv_bfloat16 d_h1hi[(size_t)Gn * NN * HD];
__device__ __nv_bfloat16 d_h1lo[(size_t)Gn * NN * HD];
__device__ __nv_bfloat16 d_wihhi[512 * 128];
__device__ __nv_bfloat16 d_wihlo[512 * 128];
__device__ float d_bsum[512];             // bih + bhh

// ---------------- CSR build ------------------------------------------------------
__global__ void zero_kernel() {
    int i = blockIdx.x * blockDim.x + threadIdx.x;
    if (i < Gn * NN) {
        d_deg_out[i] = 0.f; d_deg_in[i] = 0.f;
        d_cnt_f[i] = 0;     d_cnt_b[i] = 0;
    }
}

__global__ void degcnt_kernel(const int* __restrict__ ei, const float* __restrict__ ew) {
    int i = blockIdx.x * blockDim.x + threadIdx.x;
    if (i >= Gn * EE) return;
    int g = i / EE, e = i - g * EE;
    const int* eig = ei + (size_t)g * 2 * EE;
    int src = eig[e], dst = eig[EE + e];
    float w = ew[i];
    atomicAdd(&d_deg_out[g * NN + src], w);
    atomicAdd(&d_deg_in [g * NN + dst], w);
    atomicAdd(&d_cnt_f[g * NN + dst], 1);
    atomicAdd(&d_cnt_b[g * NN + src], 1);
}

__global__ void inv_kernel() {
    int i = blockIdx.x * blockDim.x + threadIdx.x;
    if (i >= Gn * NN) return;
    float v = d_deg_out[i];
    d_deg_out[i] = (v > 0.f) ? rsqrtf(fmaxf(v, 1e-12f)) : 0.f;
    v = d_deg_in[i];
    d_deg_in[i]  = (v > 0.f) ? rsqrtf(fmaxf(v, 1e-12f)) : 0.f;
}

__global__ void __launch_bounds__(1024) scan_kernel() {
    int g   = blockIdx.x;
    int dir = blockIdx.y;
    const int* cnt = dir ? d_cnt_b : d_cnt_f;
    int* off = dir ? d_off_b : d_off_f;
    int* cur = dir ? d_cur_b : d_cur_f;
    int tid = threadIdx.x;
    int base = g * NN;
    int v[4], tot = 0;
#pragma unroll
    for (int k = 0; k < 4; k++) {
        int i = tid * 4 + k;
        v[k] = (i < NN) ? cnt[base + i] : 0;
        tot += v[k];
    }
    __shared__ int s[1024];
    s[tid] = tot;
    __syncthreads();
    for (int d = 1; d < 1024; d <<= 1) {
        int t = (tid >= d) ? s[tid - d] : 0;
        __syncthreads();
        s[tid] += t;
        __syncthreads();
    }
    int ex = s[tid] - tot;
#pragma unroll
    for (int k = 0; k < 4; k++) {
        int i = tid * 4 + k;
        if (i < NN) { off[base + i] = ex; cur[base + i] = ex; ex += v[k]; }
    }
}

__global__ void scatter_kernel(const int* __restrict__ ei, const float* __restrict__ ew) {
    int i = blockIdx.x * blockDim.x + threadIdx.x;
    if (i >= Gn * EE) return;
    int g = i / EE, e = i - g * EE;
    const int* eig = ei + (size_t)g * 2 * EE;
    int src = eig[e], dst = eig[EE + e];
    float w = ew[i] * d_deg_out[g * NN + src] * d_deg_in[g * NN + dst];
    int pf = atomicAdd(&d_cur_f[g * NN + dst], 1);
    d_csr_if[g * EE + pf] = src;
    d_csr_wf[g * EE + pf] = w;
    int pb = atomicAdd(&d_cur_b[g * NN + src], 1);
    d_csr_ib[g * EE + pb] = dst;
    d_csr_wb[g * EE + pb] = w;
}

// ---------------- gather aggregation: one warp per (node, dir) -------------------
template<int FD>
__global__ void __launch_bounds__(256) gather_kernel(const float* __restrict__ x) {
    int gw = (blockIdx.x * 256 + threadIdx.x) >> 5;
    int lane = threadIdx.x & 31;
    if (gw >= Gn * NN * 2) return;
    int dir = gw & 1;
    int gn  = gw >> 1;
    int g   = gn / NN;
    const int*   off = dir ? d_off_b : d_off_f;
    const int*   cnt = dir ? d_cnt_b : d_cnt_f;
    const int*   nb  = dir ? d_csr_ib : d_csr_if;
    const float* wv  = dir ? d_csr_wb : d_csr_wf;
    float* outp      = dir ? d_aggb   : d_aggf;
    int o = off[gn], c = cnt[gn];
    const float* xg = x + (size_t)g * NN * FD;
    const int ebase = g * EE + o;

    if (FD == 128) {
        float4 acc = make_float4(0.f, 0.f, 0.f, 0.f);
        for (int j = 0; j < c; j++) {
            int   s = nb[ebase + j];
            float w = wv[ebase + j];
            float4 xv = *(const float4*)(xg + (size_t)s * FD + lane * 4);
            acc.x += w * xv.x; acc.y += w * xv.y;
            acc.z += w * xv.z; acc.w += w * xv.w;
        }
        *(float4*)(outp + (size_t)gn * FD + lane * 4) = acc;
    } else {
        float2 acc = make_float2(0.f, 0.f);
        for (int j = 0; j < c; j++) {
            int   s = nb[ebase + j];
            float w = wv[ebase + j];
            float2 xv = *(const float2*)(xg + (size_t)s * FD + lane * 2);
            acc.x += w * xv.x; acc.y += w * xv.y;
        }
        *(float2*)(outp + (size_t)gn * FD + lane * 2) = acc;
    }
}

// ---------------- FMA2 GEMM (round-5 winner, unchanged) -------------------------
template<int KD, bool DUAL>
__global__ void __launch_bounds__(256)
gemm2_kernel(const float* __restrict__ A0, const float* __restrict__ A1,
             const float* __restrict__ W0, const float* __restrict__ W1,
             const float* __restrict__ b0, const float* __restrict__ b1,
             float* __restrict__ C, int M, int NC,
             float s0, float s1, float bs0, float bs1)
{
    __shared__ float As[16][132];
    __shared__ float Ws[16][132];
    const int tid = threadIdx.x;
    const int m0  = blockIdx.x * 128;
    const int jn  = blockIdx.y * 128;
    const int ty  = tid >> 4;
    const int tx  = tid & 15;

    u64 acc[8][4];
#pragma unroll
    for (int r = 0; r < 8; r++)
#pragma unroll
        for (int cidx = 0; cidx < 4; cidx++) acc[r][cidx] = 0ull;

    const int npass = DUAL ? 2 : 1;
    for (int pass = 0; pass < npass; pass++) {
        const float* A = pass ? A1 : A0;
        const float* W = pass ? W1 : W0;
        const float  s = pass ? s1 : s0;
        for (int kt = 0; kt < KD; kt += 16) {
            __syncthreads();
#pragma unroll
            for (int half = 0; half < 2; half++) {
                int r  = (tid >> 2) + half * 64;
                int k4 = (tid & 3) << 2;
                float4 v = *(const float4*)(A + (size_t)(m0 + r) * KD + kt + k4);
                As[k4 + 0][r] = v.x; As[k4 + 1][r] = v.y;
                As[k4 + 2][r] = v.z; As[k4 + 3][r] = v.w;
            }
#pragma unroll
            for (int half = 0; half < 2; half++) {
                int j  = (tid >> 2) + half * 64;
                int k4 = (tid & 3) << 2;
                float4 v = *(const float4*)(W + (size_t)(jn + j) * KD + kt + k4);
                Ws[k4 + 0][j] = v.x * s; Ws[k4 + 1][j] = v.y * s;
                Ws[k4 + 2][j] = v.z * s; Ws[k4 + 3][j] = v.w * s;
            }
            __syncthreads();
#pragma unroll
            for (int kk = 0; kk < 16; kk++) {
                float a[8];
                *(float4*)&a[0] = *(const float4*)&As[kk][ty * 8];
                *(float4*)&a[4] = *(const float4*)&As[kk][ty * 8 + 4];
                float4 wA = *(const float4*)&Ws[kk][tx * 4];
                float4 wB = *(const float4*)&Ws[kk][64 + tx * 4];
                u64 w01 = *(const u64*)&wA.x;
                u64 w23 = *(const u64*)&wA.z;
                u64 w45 = *(const u64*)&wB.x;
                u64 w67 = *(const u64*)&wB.z;
#pragma unroll
                for (int r = 0; r < 8; r++) {
                    u64 aa = pack2(a[r]);
                    acc[r][0] = fma2(aa, w01, acc[r][0]);
                    acc[r][1] = fma2(aa, w23, acc[r][1]);
                    acc[r][2] = fma2(aa, w45, acc[r][2]);
                    acc[r][3] = fma2(aa, w67, acc[r][3]);
                }
            }
        }
    }

    int j1 = jn + tx * 4;
    int j2 = jn + 64 + tx * 4;
    float biasA[4], biasB[4];
#pragma unroll
    for (int cidx = 0; cidx < 4; cidx++) {
        biasA[cidx] = bs0 * b0[j1 + cidx] + bs1 * b1[j1 + cidx];
        biasB[cidx] = bs0 * b0[j2 + cidx] + bs1 * b1[j2 + cidx];
    }
#pragma unroll
    for (int r = 0; r < 8; r++) {
        int m = m0 + ty * 8 + r;
        float2 p0 = *(float2*)&acc[r][0];
        float2 p1 = *(float2*)&acc[r][1];
        float2 p2 = *(float2*)&acc[r][2];
        float2 p3 = *(float2*)&acc[r][3];
        float4 o0 = make_float4(p0.x + biasA[0], p0.y + biasA[1], p1.x + biasA[2], p1.y + biasA[3]);
        float4 o1 = make_float4(p2.x + biasB[0], p2.y + biasB[1], p3.x + biasB[2], p3.y + biasB[3]);
        *(float4*)(C + (size_t)m * NC + j1) = o0;
        *(float4*)(C + (size_t)m * NC + j2) = o1;
    }
}

// ---------------- prep: Whh^T, Wp^T, Wih hi/lo, bias sum -------------------------
__global__ void prep_kernel(const float* __restrict__ Whh, const float* __restrict__ Wp,
                            const float* __restrict__ Wih, const float* __restrict__ bih,
                            const float* __restrict__ bhh) {
    int i = blockIdx.x * blockDim.x + threadIdx.x;
    if (i < 512 * 128) {
        int j = i >> 7, k = i & 127;
        d_whhT[(size_t)k * 512 + j] = Whh[i];
        float v = Wih[i];
        __nv_bfloat16 hi = __float2bfloat16(v);
        d_wihhi[i] = hi;
        d_wihlo[i] = __float2bfloat16(v - __bfloat162float(hi));
    }
    if (i < 64 * 128) {
        int j = i >> 7, k = i & 127;
        d_wpT[k * 64 + j] = Wp[i];
    }
    if (i < 512) d_bsum[i] = bih[i] + bhh[i];
}

// ---------------- h1 fp32 -> bf16 hi/lo ------------------------------------------
__global__ void conv_kernel() {
    size_t i = (size_t)blockIdx.x * blockDim.x + threadIdx.x;   // float4 index
    if (i >= (size_t)Gn * NN * HD / 4) return;
    float4 v = ((const float4*)d_h1)[i];
    __nv_bfloat16 hx = __float2bfloat16(v.x);
    __nv_bfloat16 hy = __float2bfloat16(v.y);
    __nv_bfloat16 hz = __float2bfloat16(v.z);
    __nv_bfloat16 hw = __float2bfloat16(v.w);
    __nv_bfloat162* ph = (__nv_bfloat162*)(d_h1hi + i * 4);
    ph[0] = __nv_bfloat162(hx, hy);
    ph[1] = __nv_bfloat162(hz, hw);
    __nv_bfloat162* pl = (__nv_bfloat162*)(d_h1lo + i * 4);
    pl[0] = __nv_bfloat162(__float2bfloat16(v.x - __bfloat162float(hx)),
                           __float2bfloat16(v.y - __bfloat162float(hy)));
    pl[1] = __nv_bfloat162(__float2bfloat16(v.z - __bfloat162float(hz)),
                           __float2bfloat16(v.w - __bfloat162float(hw)));
}

// ---------------- gx GEMM via WMMA bf16x3 ----------------------------------------
// gx[128 rows x 512] = h1_tile @ Wih^T (+bias), split-bf16 3-term HMMA.
// Grid 1000 blocks, 256 threads (8 warps: 4 m-rows x 2 n-cols of 32x64 subtiles).
// Dyn smem: Ahi/Alo [128][136] bf16, Bhi/Blo [128][136] bf16, bias tile [16][128] f32.
#define LDAB 136
#define SM_AH 0
#define SM_AL (128 * LDAB * 2)
#define SM_BH (2 * 128 * LDAB * 2)
#define SM_BL (3 * 128 * LDAB * 2)
#define SM_BI (4 * 128 * LDAB * 2)
#define GX_SMEM (4 * 128 * LDAB * 2 + 16 * 128 * 4)

__global__ void __launch_bounds__(256)
gx_wmma_kernel(float* __restrict__ gx)
{
    extern __shared__ char smem[];
    __nv_bfloat16* AH = (__nv_bfloat16*)(smem + SM_AH);
    __nv_bfloat16* AL = (__nv_bfloat16*)(smem + SM_AL);
    __nv_bfloat16* BH = (__nv_bfloat16*)(smem + SM_BH);
    __nv_bfloat16* BL = (__nv_bfloat16*)(smem + SM_BL);
    float*         BI = (float*)(smem + SM_BI);

    const int tid = threadIdx.x;
    const int wid = tid >> 5;
    const int m0  = blockIdx.x * 128;
    const int m_off = (wid >> 1) * 32;     // 0,32,64,96
    const int n_off = (wid & 1) * 64;      // 0,64

    // stage A (hi/lo) once: 128 rows x 128 bf16 per image
#pragma unroll
    for (int t = 0; t < 8; t++) {
        int ch = tid + t * 256;            // 0..2047
        int r  = ch >> 4;
        int c16 = ch & 15;                 // 16B chunk (8 bf16)
        size_t gsrc = (size_t)(m0 + r) * 128 + c16 * 8;
        *(uint4*)(AH + r * LDAB + c16 * 8) = *(const uint4*)(d_h1hi + gsrc);
        *(uint4*)(AL + r * LDAB + c16 * 8) = *(const uint4*)(d_h1lo + gsrc);
    }

    for (int q = 0; q < 4; q++) {
        __syncthreads();   // previous iter done reading B / bias
        // stage B chunk q (hi/lo) + bias tile
#pragma unroll
        for (int t = 0; t < 8; t++) {
            int ch = tid + t * 256;
            int r  = ch >> 4;
            int c16 = ch & 15;
            size_t gsrc = (size_t)(q * 128 + r) * 128 + c16 * 8;
            *(uint4*)(BH + r * LDAB + c16 * 8) = *(const uint4*)(d_wihhi + gsrc);
            *(uint4*)(BL + r * LDAB + c16 * 8) = *(const uint4*)(d_wihlo + gsrc);
        }
#pragma unroll
        for (int t = 0; t < 8; t++) {
            int i = tid + t * 256;         // 0..2047
            BI[i] = d_bsum[q * 128 + (i & 127)];
        }
        __syncthreads();

        wmma::fragment<wmma::accumulator, 16, 16, 16, float> acc[2][4];
#pragma unroll
        for (int mt = 0; mt < 2; mt++)
#pragma unroll
            for (int nt = 0; nt < 4; nt++)
                wmma::load_matrix_sync(acc[mt][nt], BI + n_off + nt * 16, 128,
                                       wmma::mem_row_major);

#pragma unroll
        for (int ks = 0; ks < 8; ks++) {
            const int k0 = ks * 16;
            wmma::fragment<wmma::matrix_a, 16, 16, 16, __nv_bfloat16, wmma::row_major> ah[2], al[2];
            wmma::fragment<wmma::matrix_b, 16, 16, 16, __nv_bfloat16, wmma::col_major> bh[4], bl[4];
#pragma unroll
            for (int mt = 0; mt < 2; mt++) {
                wmma::load_matrix_sync(ah[mt], AH + (m_off + mt * 16) * LDAB + k0, LDAB);
                wmma::load_matrix_sync(al[mt], AL + (m_off + mt * 16) * LDAB + k0, LDAB);
            }
#pragma unroll
            for (int nt = 0; nt < 4; nt++) {
                wmma::load_matrix_sync(bh[nt], BH + (n_off + nt * 16) * LDAB + k0, LDAB);
                wmma::load_matrix_sync(bl[nt], BL + (n_off + nt * 16) * LDAB + k0, LDAB);
            }
#pragma unroll
            for (int mt = 0; mt < 2; mt++)
#pragma unroll
                for (int nt = 0; nt < 4; nt++) {
                    wmma::mma_sync(acc[mt][nt], ah[mt], bh[nt], acc[mt][nt]);
                    wmma::mma_sync(acc[mt][nt], ah[mt], bl[nt], acc[mt][nt]);
                    wmma::mma_sync(acc[mt][nt], al[mt], bh[nt], acc[mt][nt]);
                }
        }

#pragma unroll
        for (int mt = 0; mt < 2; mt++)
#pragma unroll
            for (int nt = 0; nt < 4; nt++)
                wmma::store_matrix_sync(
                    gx + (size_t)(m0 + m_off + mt * 16) * 512 + q * 128 + n_off + nt * 16,
                    acc[mt][nt], 512, wmma::mem_row_major);
    }
}

// ---------------- LSTM recurrence + fused projection (round-5, unchanged) --------
__device__ __forceinline__ float sigmoidf_(float x) { return 1.f / (1.f + __expf(-x)); }

__global__ void __launch_bounds__(256)
lstm_kernel(float* __restrict__ out, const float* __restrict__ bp)
{
    __shared__ float h_s[32][128];
    __shared__ float w_s[16][512];
    const int tid  = threadIdx.x;
    const int tc   = tid & 31;
    const int tr   = tid >> 5;
    const int row0 = blockIdx.x * 32 + tr * 4;

    float c[4][4];
#pragma unroll
    for (int a = 0; a < 4; a++)
#pragma unroll
        for (int b = 0; b < 4; b++) c[a][b] = 0.f;

    for (int t = 0; t < STEPS; t++) {
        u64 acc[4][4][2];
#pragma unroll
        for (int gate = 0; gate < 4; gate++)
#pragma unroll
            for (int ri = 0; ri < 4; ri++) {
                float4 v = *(const float4*)(d_gx +
                    ((size_t)(row0 + ri) * STEPS + t) * 512 + gate * 128 + tc * 4);
                acc[gate][ri][0] = *(const u64*)&v.x;
                acc[gate][ri][1] = *(const u64*)&v.z;
            }

        if (t > 0) {
            for (int kt = 0; kt < 8; kt++) {
                __syncthreads();
#pragma unroll
                for (int i = 0; i < 8; i++) {
                    int q  = tid + i * 256;
                    int kk = q >> 7;
                    int j4 = (q & 127) << 2;
                    *(float4*)&w_s[kk][j4] =
                        *(const float4*)(d_whhT + (size_t)(kt * 16 + kk) * 512 + j4);
                }
                __syncthreads();
#pragma unroll
                for (int kk = 0; kk < 16; kk++) {
                    u64 hp[4];
#pragma unroll
                    for (int ri = 0; ri < 4; ri++)
                        hp[ri] = pack2(h_s[tr * 4 + ri][kt * 16 + kk]);
#pragma unroll
                    for (int gate = 0; gate < 4; gate++) {
                        float4 w = *(const float4*)&w_s[kk][gate * 128 + tc * 4];
                        u64 w01 = *(const u64*)&w.x;
                        u64 w23 = *(const u64*)&w.z;
#pragma unroll
                        for (int ri = 0; ri < 4; ri++) {
                            acc[gate][ri][0] = fma2(hp[ri], w01, acc[gate][ri][0]);
                            acc[gate][ri][1] = fma2(hp[ri], w23, acc[gate][ri][1]);
                        }
                    }
                }
            }
            __syncthreads();
        }

#pragma unroll
        for (int ri = 0; ri < 4; ri++) {
            float2 i01 = *(float2*)&acc[0][ri][0], i23 = *(float2*)&acc[0][ri][1];
            float2 f01 = *(float2*)&acc[1][ri][0], f23 = *(float2*)&acc[1][ri][1];
            float2 g01 = *(float2*)&acc[2][ri][0], g23 = *(float2*)&acc[2][ri][1];
            float2 o01 = *(float2*)&acc[3][ri][0], o23 = *(float2*)&acc[3][ri][1];
            float ig[4] = {i01.x, i01.y, i23.x, i23.y};
            float fg[4] = {f01.x, f01.y, f23.x, f23.y};
            float gg[4] = {g01.x, g01.y, g23.x, g23.y};
            float og[4] = {o01.x, o01.y, o23.x, o23.y};
            float hn[4];
#pragma unroll
            for (int ci = 0; ci < 4; ci++) {
                float iv = sigmoidf_(ig[ci]);
                float fv = sigmoidf_(fg[ci]);
                float gv = tanhf(gg[ci]);
                float ov = sigmoidf_(og[ci]);
                float cn = fv * c[ri][ci] + iv * gv;
                c[ri][ci] = cn;
                hn[ci] = ov * tanhf(cn);
            }
            *(float4*)&h_s[tr * 4 + ri][tc * 4] = make_float4(hn[0], hn[1], hn[2], hn[3]);
        }
        __syncthreads();
    }

    float* wp = &w_s[0][0];
#pragma unroll
    for (int i = 0; i < 8; i++) {
        int q = tid + i * 256;
        *(float4*)&wp[q * 4] = *(const float4*)(d_wpT + q * 4);
    }
    __syncthreads();

    const int prow = tid >> 3;
    const int cg   = tid & 7;
    const int orow = blockIdx.x * 32 + prow;
    u64 pacc[4] = {0ull, 0ull, 0ull, 0ull};
#pragma unroll 8
    for (int k = 0; k < 128; k++) {
        u64 hv = pack2(h_s[prow][k]);
        float4 wa = *(const float4*)&wp[k * 64 + cg * 8];
        float4 wb = *(const float4*)&wp[k * 64 + cg * 8 + 4];
        pacc[0] = fma2(hv, *(const u64*)&wa.x, pacc[0]);
        pacc[1] = fma2(hv, *(const u64*)&wa.z, pacc[1]);
        pacc[2] = fma2(hv, *(const u64*)&wb.x, pacc[2]);
        pacc[3] = fma2(hv, *(const u64*)&wb.z, pacc[3]);
    }
    float4 bpa = *(const float4*)(bp + cg * 8);
    float4 bpb = *(const float4*)(bp + cg * 8 + 4);
    float2 q0 = *(float2*)&pacc[0];
    float2 q1 = *(float2*)&pacc[1];
    float2 q2 = *(float2*)&pacc[2];
    float2 q3 = *(float2*)&pacc[3];
    float4 o0 = make_float4(q0.x + bpa.x, q0.y + bpa.y, q1.x + bpa.z, q1.y + bpa.w);
    float4 o1 = make_float4(q2.x + bpb.x, q2.y + bpb.y, q3.x + bpb.z, q3.y + bpb.w);
    *(float4*)(out + (size_t)orow * 64 + cg * 8)     = o0;
    *(float4*)(out + (size_t)orow * 64 + cg * 8 + 4) = o1;
}

// ---------------- launch --------------------------------------------------------
extern "C" void kernel_launch(void* const* d_in, const int* in_sizes, int n_in,
                              void* d_out, int out_size)
{
    const float* x_seq = (const float*)d_in[0];
    const int*   ei    = (const int*)  d_in[1];
    const float* ew    = (const float*)d_in[2];
    const float* W0s   = (const float*)d_in[3];
    const float* b0s   = (const float*)d_in[4];
    const float* W0d   = (const float*)d_in[5];
    const float* b0d   = (const float*)d_in[6];
    const float* W1s   = (const float*)d_in[7];
    const float* b1s   = (const float*)d_in[8];
    const float* W1d   = (const float*)d_in[9];
    const float* b1d   = (const float*)d_in[10];
    const float* Wih   = (const float*)d_in[11];
    const float* Whh   = (const float*)d_in[12];
    const float* bih   = (const float*)d_in[13];
    const float* bhh   = (const float*)d_in[14];
    const float* Wp    = (const float*)d_in[15];
    const float* bp    = (const float*)d_in[16];
    float* out = (float*)d_out;

    float *aggf, *aggb, *h0, *h1, *gx;
    cudaGetSymbolAddress((void**)&aggf, d_aggf);
    cudaGetSymbolAddress((void**)&aggb, d_aggb);
    cudaGetSymbolAddress((void**)&h0,   d_h0);
    cudaGetSymbolAddress((void**)&h1,   d_h1);
    cudaGetSymbolAddress((void**)&gx,   d_gx);

    cudaFuncSetAttribute(gx_wmma_kernel,
                         cudaFuncAttributeMaxDynamicSharedMemorySize, GX_SMEM);

    const int M = Gn * NN;   // 128000

    // ---- CSR build ----
    zero_kernel<<<(Gn * NN + 255) / 256, 256>>>();
    degcnt_kernel<<<(Gn * EE + 255) / 256, 256>>>(ei, ew);
    inv_kernel<<<(Gn * NN + 255) / 256, 256>>>();
    scan_kernel<<<dim3(Gn, 2), 1024>>>();
    scatter_kernel<<<(Gn * EE + 255) / 256, 256>>>(ei, ew);

    const int gblocks = (Gn * NN * 2 * 32 + 255) / 256;

    // ---- GCN layer 0 (F=64 -> H=128) ----
    gather_kernel<64><<<gblocks, 256>>>(x_seq);
    gemm2_kernel<64, true><<<dim3(M / 128, 1), 256>>>(
        aggf, aggb, W0s, W0d, b0s, b0d, h0, M, HD, 0.5f, 0.5f, 0.5f, 0.5f);

    // ---- GCN layer 1 (H=128 -> H=128) ----
    gather_kernel<128><<<gblocks, 256>>>(h0);
    gemm2_kernel<128, true><<<dim3(M / 128, 1), 256>>>(
        aggf, aggb, W1s, W1d, b1s, b1d, h1, M, HD, 0.5f, 0.5f, 0.5f, 0.5f);

    // ---- LSTM input GEMM via WMMA bf16x3 ----
    prep_kernel<<<256, 256>>>(Whh, Wp, Wih, bih, bhh);
    conv_kernel<<<(int)(((size_t)Gn * NN * HD / 4 + 255) / 256), 256>>>();
    gx_wmma_kernel<<<M / 128, 256, GX_SMEM>>>(gx);

    // ---- LSTM recurrence + fused projection ----
    lstm_kernel<<<BNR / 32, 256>>>(out, bp);
}

// round 11
// speedup vs baseline: 1.6414x; 1.0466x over previous
#include <cuda_runtime.h>
#include <cuda_bf16.h>
#include <mma.h>

using namespace nvcuda;

// Problem dims (fixed by the reference)
#define Gn   32
#define NN   4000
#define EE   32000
#define FD0  64
#define HD   128
#define BNR  16000
#define STEPS 8

typedef unsigned long long u64;

__device__ __forceinline__ u64 fma2(u64 a, u64 b, u64 c) {
    u64 d;
    asm("fma.rn.f32x2 %0, %1, %2, %3;" : "=l"(d) : "l"(a), "l"(b), "l"(c));
    return d;
}
__device__ __forceinline__ u64 pack2(float x) {
    u64 d; asm("mov.b64 %0, {%1, %1};" : "=l"(d) : "f"(x)); return d;
}
__device__ __forceinline__ void split_bf16(float v, __nv_bfloat16& hi, __nv_bfloat16& lo) {
    hi = __float2bfloat16(v);
    lo = __float2bfloat16(v - __bfloat162float(hi));
}

// ---------------- scratch (device globals) --------------------------------------
__device__ float d_deg_out[Gn * NN];
__device__ float d_deg_in [Gn * NN];
__device__ int   d_cnt_f[Gn * NN];
__device__ int   d_cnt_b[Gn * NN];
__device__ int   d_off_f[Gn * NN];
__device__ int   d_off_b[Gn * NN];
__device__ int   d_cur_f[Gn * NN];
__device__ int   d_cur_b[Gn * NN];
__device__ int   d_csr_if[Gn * EE];
__device__ float d_csr_wf[Gn * EE];
__device__ int   d_csr_ib[Gn * EE];
__device__ float d_csr_wb[Gn * EE];
// aggregation outputs, bf16 hi/lo (used at FD=64 for layer0, FD=128 for layer1)
__device__ __nv_bfloat16 d_aggfh[(size_t)Gn * NN * HD];
__device__ __nv_bfloat16 d_aggfl[(size_t)Gn * NN * HD];
__device__ __nv_bfloat16 d_aggbh[(size_t)Gn * NN * HD];
__device__ __nv_bfloat16 d_aggbl[(size_t)Gn * NN * HD];
__device__ float d_h0    [(size_t)Gn * NN * HD];
__device__ float d_h1    [(size_t)Gn * NN * HD];
__device__ float d_gx    [(size_t)BNR * STEPS * 4 * HD];
__device__ float d_whhT  [HD * 4 * HD];   // Whh^T [128][512]
__device__ float d_wpT   [HD * FD0];      // Wp^T  [128][64]
// bf16x3 weight/input images
__device__ __nv_bfloat16 d_h1hi[(size_t)Gn * NN * HD];
__device__ __nv_bfloat16 d_h1lo[(size_t)Gn * NN * HD];
__device__ __nv_bfloat16 d_wihhi[512 * 128];
__device__ __nv_bfloat16 d_wihlo[512 * 128];
__device__ float d_bsum[512];             // bih + bhh
__device__ __nv_bfloat16 d_w0sh[HD * FD0], d_w0sl[HD * FD0];   // 0.5*W0s hi/lo
__device__ __nv_bfloat16 d_w0dh[HD * FD0], d_w0dl[HD * FD0];
__device__ __nv_bfloat16 d_w1sh[HD * HD],  d_w1sl[HD * HD];
__device__ __nv_bfloat16 d_w1dh[HD * HD],  d_w1dl[HD * HD];
__device__ float d_b0v[HD];               // 0.5*(b0s+b0d)
__device__ float d_b1v[HD];

// ---------------- CSR build ------------------------------------------------------
__global__ void zero_kernel() {
    int i = blockIdx.x * blockDim.x + threadIdx.x;
    if (i < Gn * NN) {
        d_deg_out[i] = 0.f; d_deg_in[i] = 0.f;
        d_cnt_f[i] = 0;     d_cnt_b[i] = 0;
    }
}

__global__ void degcnt_kernel(const int* __restrict__ ei, const float* __restrict__ ew) {
    int i = blockIdx.x * blockDim.x + threadIdx.x;
    if (i >= Gn * EE) return;
    int g = i / EE, e = i - g * EE;
    const int* eig = ei + (size_t)g * 2 * EE;
    int src = eig[e], dst = eig[EE + e];
    float w = ew[i];
    atomicAdd(&d_deg_out[g * NN + src], w);
    atomicAdd(&d_deg_in [g * NN + dst], w);
    atomicAdd(&d_cnt_f[g * NN + dst], 1);
    atomicAdd(&d_cnt_b[g * NN + src], 1);
}

__global__ void inv_kernel() {
    int i = blockIdx.x * blockDim.x + threadIdx.x;
    if (i >= Gn * NN) return;
    float v = d_deg_out[i];
    d_deg_out[i] = (v > 0.f) ? rsqrtf(fmaxf(v, 1e-12f)) : 0.f;
    v = d_deg_in[i];
    d_deg_in[i]  = (v > 0.f) ? rsqrtf(fmaxf(v, 1e-12f)) : 0.f;
}

__global__ void __launch_bounds__(1024) scan_kernel() {
    int g   = blockIdx.x;
    int dir = blockIdx.y;
    const int* cnt = dir ? d_cnt_b : d_cnt_f;
    int* off = dir ? d_off_b : d_off_f;
    int* cur = dir ? d_cur_b : d_cur_f;
    int tid = threadIdx.x;
    int base = g * NN;
    int v[4], tot = 0;
#pragma unroll
    for (int k = 0; k < 4; k++) {
        int i = tid * 4 + k;
        v[k] = (i < NN) ? cnt[base + i] : 0;
        tot += v[k];
    }
    __shared__ int s[1024];
    s[tid] = tot;
    __syncthreads();
    for (int d = 1; d < 1024; d <<= 1) {
        int t = (tid >= d) ? s[tid - d] : 0;
        __syncthreads();
        s[tid] += t;
        __syncthreads();
    }
    int ex = s[tid] - tot;
#pragma unroll
    for (int k = 0; k < 4; k++) {
        int i = tid * 4 + k;
        if (i < NN) { off[base + i] = ex; cur[base + i] = ex; ex += v[k]; }
    }
}

__global__ void scatter_kernel(const int* __restrict__ ei, const float* __restrict__ ew) {
    int i = blockIdx.x * blockDim.x + threadIdx.x;
    if (i >= Gn * EE) return;
    int g = i / EE, e = i - g * EE;
    const int* eig = ei + (size_t)g * 2 * EE;
    int src = eig[e], dst = eig[EE + e];
    float w = ew[i] * d_deg_out[g * NN + src] * d_deg_in[g * NN + dst];
    int pf = atomicAdd(&d_cur_f[g * NN + dst], 1);
    d_csr_if[g * EE + pf] = src;
    d_csr_wf[g * EE + pf] = w;
    int pb = atomicAdd(&d_cur_b[g * NN + src], 1);
    d_csr_ib[g * EE + pb] = dst;
    d_csr_wb[g * EE + pb] = w;
}

// ---------------- gather aggregation: one warp per (node, dir), bf16 hi/lo out ---
template<int FD>
__global__ void __launch_bounds__(256) gather_kernel(const float* __restrict__ x) {
    int gw = (blockIdx.x * 256 + threadIdx.x) >> 5;
    int lane = threadIdx.x & 31;
    if (gw >= Gn * NN * 2) return;
    int dir = gw & 1;
    int gn  = gw >> 1;
    int g   = gn / NN;
    const int*   off = dir ? d_off_b : d_off_f;
    const int*   cnt = dir ? d_cnt_b : d_cnt_f;
    const int*   nb  = dir ? d_csr_ib : d_csr_if;
    const float* wv  = dir ? d_csr_wb : d_csr_wf;
    __nv_bfloat16* oh = dir ? d_aggbh : d_aggfh;
    __nv_bfloat16* ol = dir ? d_aggbl : d_aggfl;
    int o = off[gn], c = cnt[gn];
    const float* xg = x + (size_t)g * NN * FD;
    const int ebase = g * EE + o;

    if (FD == 128) {
        float4 acc = make_float4(0.f, 0.f, 0.f, 0.f);
        for (int j = 0; j < c; j++) {
            int   s = nb[ebase + j];
            float w = wv[ebase + j];
            float4 xv = *(const float4*)(xg + (size_t)s * FD + lane * 4);
            acc.x += w * xv.x; acc.y += w * xv.y;
            acc.z += w * xv.z; acc.w += w * xv.w;
        }
        __nv_bfloat16 hx, lx, hy, ly, hz, lz, hw, lw;
        split_bf16(acc.x, hx, lx); split_bf16(acc.y, hy, ly);
        split_bf16(acc.z, hz, lz); split_bf16(acc.w, hw, lw);
        size_t p = (size_t)gn * FD + lane * 4;
        *(__nv_bfloat162*)(oh + p)     = __nv_bfloat162(hx, hy);
        *(__nv_bfloat162*)(oh + p + 2) = __nv_bfloat162(hz, hw);
        *(__nv_bfloat162*)(ol + p)     = __nv_bfloat162(lx, ly);
        *(__nv_bfloat162*)(ol + p + 2) = __nv_bfloat162(lz, lw);
    } else {
        float2 acc = make_float2(0.f, 0.f);
        for (int j = 0; j < c; j++) {
            int   s = nb[ebase + j];
            float w = wv[ebase + j];
            float2 xv = *(const float2*)(xg + (size_t)s * FD + lane * 2);
            acc.x += w * xv.x; acc.y += w * xv.y;
        }
        __nv_bfloat16 hx, lx, hy, ly;
        split_bf16(acc.x, hx, lx); split_bf16(acc.y, hy, ly);
        size_t p = (size_t)gn * FD + lane * 2;
        *(__nv_bfloat162*)(oh + p) = __nv_bfloat162(hx, hy);
        *(__nv_bfloat162*)(ol + p) = __nv_bfloat162(lx, ly);
    }
}

// ---------------- GCN dual GEMM via WMMA bf16x3 ----------------------------------
// C[128 x 128] = sum_dir Adir @ Wdir^T + bias. Weights pre-scaled by 0.5, pre-split.
// 8 warps: 4 m-rows x 2 n-cols of 32x64 subtiles. Grid 1000 blocks.
template<int KD>
__global__ void __launch_bounds__(256)
gcn_wmma_kernel(const __nv_bfloat16* __restrict__ A0h, const __nv_bfloat16* __restrict__ A0l,
                const __nv_bfloat16* __restrict__ A1h, const __nv_bfloat16* __restrict__ A1l,
                const __nv_bfloat16* __restrict__ W0h, const __nv_bfloat16* __restrict__ W0l,
                const __nv_bfloat16* __restrict__ W1h, const __nv_bfloat16* __restrict__ W1l,
                const float* __restrict__ bias, float* __restrict__ C)
{
    constexpr int LD = KD + 8;
    extern __shared__ char smem[];
    __nv_bfloat16* AH = (__nv_bfloat16*)smem;
    __nv_bfloat16* AL = AH + 128 * LD;
    __nv_bfloat16* BH = AL + 128 * LD;
    __nv_bfloat16* BL = BH + 128 * LD;
    float*         BI = (float*)(BL + 128 * LD);

    const int tid = threadIdx.x;
    const int wid = tid >> 5;
    const int m0  = blockIdx.x * 128;
    const int m_off = (wid >> 1) * 32;
    const int n_off = (wid & 1) * 64;
    constexpr int CPR = KD / 8;          // 16B chunks per row

#pragma unroll
    for (int t = 0; t < 8; t++) {
        int i = tid + t * 256;
        BI[i] = bias[i & 127];
    }

    wmma::fragment<wmma::accumulator, 16, 16, 16, float> acc[2][4];

    for (int dir = 0; dir < 2; dir++) {
        const __nv_bfloat16* Ah = dir ? A1h : A0h;
        const __nv_bfloat16* Al = dir ? A1l : A0l;
        const __nv_bfloat16* Wh = dir ? W1h : W0h;
        const __nv_bfloat16* Wl = dir ? W1l : W0l;
        if (dir) __syncthreads();        // previous compute done reading smem
#pragma unroll
        for (int t = 0; t < KD / 16; t++) {
            int ch = tid + t * 256;
            int r  = ch / CPR;
            int c8 = ch % CPR;
            *(uint4*)(AH + r * LD + c8 * 8) = *(const uint4*)(Ah + (size_t)(m0 + r) * KD + c8 * 8);
            *(uint4*)(AL + r * LD + c8 * 8) = *(const uint4*)(Al + (size_t)(m0 + r) * KD + c8 * 8);
            *(uint4*)(BH + r * LD + c8 * 8) = *(const uint4*)(Wh + (size_t)r * KD + c8 * 8);
            *(uint4*)(BL + r * LD + c8 * 8) = *(const uint4*)(Wl + (size_t)r * KD + c8 * 8);
        }
        __syncthreads();

        if (dir == 0) {
#pragma unroll
            for (int mt = 0; mt < 2; mt++)
#pragma unroll
                for (int nt = 0; nt < 4; nt++)
                    wmma::load_matrix_sync(acc[mt][nt], BI + n_off + nt * 16, 128,
                                           wmma::mem_row_major);
        }

#pragma unroll
        for (int ks = 0; ks < KD / 16; ks++) {
            const int k0 = ks * 16;
            wmma::fragment<wmma::matrix_a, 16, 16, 16, __nv_bfloat16, wmma::row_major> ah[2], al[2];
            wmma::fragment<wmma::matrix_b, 16, 16, 16, __nv_bfloat16, wmma::col_major> bh[4], bl[4];
#pragma unroll
            for (int mt = 0; mt < 2; mt++) {
                wmma::load_matrix_sync(ah[mt], AH + (m_off + mt * 16) * LD + k0, LD);
                wmma::load_matrix_sync(al[mt], AL + (m_off + mt * 16) * LD + k0, LD);
            }
#pragma unroll
            for (int nt = 0; nt < 4; nt++) {
                wmma::load_matrix_sync(bh[nt], BH + (n_off + nt * 16) * LD + k0, LD);
                wmma::load_matrix_sync(bl[nt], BL + (n_off + nt * 16) * LD + k0, LD);
            }
#pragma unroll
            for (int mt = 0; mt < 2; mt++)
#pragma unroll
                for (int nt = 0; nt < 4; nt++) {
                    wmma::mma_sync(acc[mt][nt], ah[mt], bh[nt], acc[mt][nt]);
                    wmma::mma_sync(acc[mt][nt], ah[mt], bl[nt], acc[mt][nt]);
                    wmma::mma_sync(acc[mt][nt], al[mt], bh[nt], acc[mt][nt]);
                }
        }
    }

#pragma unroll
    for (int mt = 0; mt < 2; mt++)
#pragma unroll
        for (int nt = 0; nt < 4; nt++)
            wmma::store_matrix_sync(
                C + (size_t)(m0 + m_off + mt * 16) * 128 + n_off + nt * 16,
                acc[mt][nt], 128, wmma::mem_row_major);
}

// ---------------- prep: all weight images + bias sums ----------------------------
__global__ void prep_kernel(const float* __restrict__ Whh, const float* __restrict__ Wp,
                            const float* __restrict__ Wih, const float* __restrict__ bih,
                            const float* __restrict__ bhh,
                            const float* __restrict__ W0s, const float* __restrict__ W0d,
                            const float* __restrict__ W1s, const float* __restrict__ W1d,
                            const float* __restrict__ b0s, const float* __restrict__ b0d,
                            const float* __restrict__ b1s, const float* __restrict__ b1d) {
    int i = blockIdx.x * blockDim.x + threadIdx.x;
    if (i < 512 * 128) {
        int j = i >> 7, k = i & 127;
        d_whhT[(size_t)k * 512 + j] = Whh[i];
        split_bf16(Wih[i], d_wihhi[i], d_wihlo[i]);
    }
    if (i < 128 * 64) {
        split_bf16(0.5f * W0s[i], d_w0sh[i], d_w0sl[i]);
        split_bf16(0.5f * W0d[i], d_w0dh[i], d_w0dl[i]);
    }
    if (i < 128 * 128) {
        split_bf16(0.5f * W1s[i], d_w1sh[i], d_w1sl[i]);
        split_bf16(0.5f * W1d[i], d_w1dh[i], d_w1dl[i]);
    }
    if (i < 64 * 128) {
        int j = i >> 7, k = i & 127;
        d_wpT[k * 64 + j] = Wp[i];
    }
    if (i < 512) d_bsum[i] = bih[i] + bhh[i];
    if (i < 128) {
        d_b0v[i] = 0.5f * (b0s[i] + b0d[i]);
        d_b1v[i] = 0.5f * (b1s[i] + b1d[i]);
    }
}

// ---------------- h1 fp32 -> bf16 hi/lo ------------------------------------------
__global__ void conv_kernel() {
    size_t i = (size_t)blockIdx.x * blockDim.x + threadIdx.x;   // float4 index
    if (i >= (size_t)Gn * NN * HD / 4) return;
    float4 v = ((const float4*)d_h1)[i];
    __nv_bfloat16 hx, lx, hy, ly, hz, lz, hw, lw;
    split_bf16(v.x, hx, lx); split_bf16(v.y, hy, ly);
    split_bf16(v.z, hz, lz); split_bf16(v.w, hw, lw);
    __nv_bfloat162* ph = (__nv_bfloat162*)(d_h1hi + i * 4);
    ph[0] = __nv_bfloat162(hx, hy);
    ph[1] = __nv_bfloat162(hz, hw);
    __nv_bfloat162* pl = (__nv_bfloat162*)(d_h1lo + i * 4);
    pl[0] = __nv_bfloat162(lx, ly);
    pl[1] = __nv_bfloat162(lz, lw);
}

// ---------------- gx GEMM via WMMA bf16x3 (round-10 winner, unchanged) -----------
#define LDAB 136
#define SM_AH 0
#define SM_AL (128 * LDAB * 2)
#define SM_BH (2 * 128 * LDAB * 2)
#define SM_BL (3 * 128 * LDAB * 2)
#define SM_BI (4 * 128 * LDAB * 2)
#define GX_SMEM (4 * 128 * LDAB * 2 + 16 * 128 * 4)

__global__ void __launch_bounds__(256)
gx_wmma_kernel(float* __restrict__ gx)
{
    extern __shared__ char smem[];
    __nv_bfloat16* AH = (__nv_bfloat16*)(smem + SM_AH);
    __nv_bfloat16* AL = (__nv_bfloat16*)(smem + SM_AL);
    __nv_bfloat16* BH = (__nv_bfloat16*)(smem + SM_BH);
    __nv_bfloat16* BL = (__nv_bfloat16*)(smem + SM_BL);
    float*         BI = (float*)(smem + SM_BI);

    const int tid = threadIdx.x;
    const int wid = tid >> 5;
    const int m0  = blockIdx.x * 128;
    const int m_off = (wid >> 1) * 32;
    const int n_off = (wid & 1) * 64;

#pragma unroll
    for (int t = 0; t < 8; t++) {
        int ch = tid + t * 256;
        int r  = ch >> 4;
        int c16 = ch & 15;
        size_t gsrc = (size_t)(m0 + r) * 128 + c16 * 8;
        *(uint4*)(AH + r * LDAB + c16 * 8) = *(const uint4*)(d_h1hi + gsrc);
        *(uint4*)(AL + r * LDAB + c16 * 8) = *(const uint4*)(d_h1lo + gsrc);
    }

    for (int q = 0; q < 4; q++) {
        __syncthreads();
#pragma unroll
        for (int t = 0; t < 8; t++) {
            int ch = tid + t * 256;
            int r  = ch >> 4;
            int c16 = ch & 15;
            size_t gsrc = (size_t)(q * 128 + r) * 128 + c16 * 8;
            *(uint4*)(BH + r * LDAB + c16 * 8) = *(const uint4*)(d_wihhi + gsrc);
            *(uint4*)(BL + r * LDAB + c16 * 8) = *(const uint4*)(d_wihlo + gsrc);
        }
#pragma unroll
        for (int t = 0; t < 8; t++) {
            int i = tid + t * 256;
            BI[i] = d_bsum[q * 128 + (i & 127)];
        }
        __syncthreads();

        wmma::fragment<wmma::accumulator, 16, 16, 16, float> acc[2][4];
#pragma unroll
        for (int mt = 0; mt < 2; mt++)
#pragma unroll
            for (int nt = 0; nt < 4; nt++)
                wmma::load_matrix_sync(acc[mt][nt], BI + n_off + nt * 16, 128,
                                       wmma::mem_row_major);

#pragma unroll
        for (int ks = 0; ks < 8; ks++) {
            const int k0 = ks * 16;
            wmma::fragment<wmma::matrix_a, 16, 16, 16, __nv_bfloat16, wmma::row_major> ah[2], al[2];
            wmma::fragment<wmma::matrix_b, 16, 16, 16, __nv_bfloat16, wmma::col_major> bh[4], bl[4];
#pragma unroll
            for (int mt = 0; mt < 2; mt++) {
                wmma::load_matrix_sync(ah[mt], AH + (m_off + mt * 16) * LDAB + k0, LDAB);
                wmma::load_matrix_sync(al[mt], AL + (m_off + mt * 16) * LDAB + k0, LDAB);
            }
#pragma unroll
            for (int nt = 0; nt < 4; nt++) {
                wmma::load_matrix_sync(bh[nt], BH + (n_off + nt * 16) * LDAB + k0, LDAB);
                wmma::load_matrix_sync(bl[nt], BL + (n_off + nt * 16) * LDAB + k0, LDAB);
            }
#pragma unroll
            for (int mt = 0; mt < 2; mt++)
#pragma unroll
                for (int nt = 0; nt < 4; nt++) {
                    wmma::mma_sync(acc[mt][nt], ah[mt], bh[nt], acc[mt][nt]);
                    wmma::mma_sync(acc[mt][nt], ah[mt], bl[nt], acc[mt][nt]);
                    wmma::mma_sync(acc[mt][nt], al[mt], bh[nt], acc[mt][nt]);
                }
        }

#pragma unroll
        for (int mt = 0; mt < 2; mt++)
#pragma unroll
            for (int nt = 0; nt < 4; nt++)
                wmma::store_matrix_sync(
                    gx + (size_t)(m0 + m_off + mt * 16) * 512 + q * 128 + n_off + nt * 16,
                    acc[mt][nt], 512, wmma::mem_row_major);
    }
}

// ---------------- LSTM recurrence + fused projection (unchanged) -----------------
__device__ __forceinline__ float sigmoidf_(float x) { return 1.f / (1.f + __expf(-x)); }

__global__ void __launch_bounds__(256)
lstm_kernel(float* __restrict__ out, const float* __restrict__ bp)
{
    __shared__ float h_s[32][128];
    __shared__ float w_s[16][512];
    const int tid  = threadIdx.x;
    const int tc   = tid & 31;
    const int tr   = tid >> 5;
    const int row0 = blockIdx.x * 32 + tr * 4;

    float c[4][4];
#pragma unroll
    for (int a = 0; a < 4; a++)
#pragma unroll
        for (int b = 0; b < 4; b++) c[a][b] = 0.f;

    for (int t = 0; t < STEPS; t++) {
        u64 acc[4][4][2];
#pragma unroll
        for (int gate = 0; gate < 4; gate++)
#pragma unroll
            for (int ri = 0; ri < 4; ri++) {
                float4 v = *(const float4*)(d_gx +
                    ((size_t)(row0 + ri) * STEPS + t) * 512 + gate * 128 + tc * 4);
                acc[gate][ri][0] = *(const u64*)&v.x;
                acc[gate][ri][1] = *(const u64*)&v.z;
            }

        if (t > 0) {
            for (int kt = 0; kt < 8; kt++) {
                __syncthreads();
#pragma unroll
                for (int i = 0; i < 8; i++) {
                    int q  = tid + i * 256;
                    int kk = q >> 7;
                    int j4 = (q & 127) << 2;
                    *(float4*)&w_s[kk][j4] =
                        *(const float4*)(d_whhT + (size_t)(kt * 16 + kk) * 512 + j4);
                }
                __syncthreads();
#pragma unroll
                for (int kk = 0; kk < 16; kk++) {
                    u64 hp[4];
#pragma unroll
                    for (int ri = 0; ri < 4; ri++)
                        hp[ri] = pack2(h_s[tr * 4 + ri][kt * 16 + kk]);
#pragma unroll
                    for (int gate = 0; gate < 4; gate++) {
                        float4 w = *(const float4*)&w_s[kk][gate * 128 + tc * 4];
                        u64 w01 = *(const u64*)&w.x;
                        u64 w23 = *(const u64*)&w.z;
#pragma unroll
                        for (int ri = 0; ri < 4; ri++) {
                            acc[gate][ri][0] = fma2(hp[ri], w01, acc[gate][ri][0]);
                            acc[gate][ri][1] = fma2(hp[ri], w23, acc[gate][ri][1]);
                        }
                    }
                }
            }
            __syncthreads();
        }

#pragma unroll
        for (int ri = 0; ri < 4; ri++) {
            float2 i01 = *(float2*)&acc[0][ri][0], i23 = *(float2*)&acc[0][ri][1];
            float2 f01 = *(float2*)&acc[1][ri][0], f23 = *(float2*)&acc[1][ri][1];
            float2 g01 = *(float2*)&acc[2][ri][0], g23 = *(float2*)&acc[2][ri][1];
            float2 o01 = *(float2*)&acc[3][ri][0], o23 = *(float2*)&acc[3][ri][1];
            float ig[4] = {i01.x, i01.y, i23.x, i23.y};
            float fg[4] = {f01.x, f01.y, f23.x, f23.y};
            float gg[4] = {g01.x, g01.y, g23.x, g23.y};
            float og[4] = {o01.x, o01.y, o23.x, o23.y};
            float hn[4];
#pragma unroll
            for (int ci = 0; ci < 4; ci++) {
                float iv = sigmoidf_(ig[ci]);
                float fv = sigmoidf_(fg[ci]);
                float gv = tanhf(gg[ci]);
                float ov = sigmoidf_(og[ci]);
                float cn = fv * c[ri][ci] + iv * gv;
                c[ri][ci] = cn;
                hn[ci] = ov * tanhf(cn);
            }
            *(float4*)&h_s[tr * 4 + ri][tc * 4] = make_float4(hn[0], hn[1], hn[2], hn[3]);
        }
        __syncthreads();
    }

    float* wp = &w_s[0][0];
#pragma unroll
    for (int i = 0; i < 8; i++) {
        int q = tid + i * 256;
        *(float4*)&wp[q * 4] = *(const float4*)(d_wpT + q * 4);
    }
    __syncthreads();

    const int prow = tid >> 3;
    const int cg   = tid & 7;
    const int orow = blockIdx.x * 32 + prow;
    u64 pacc[4] = {0ull, 0ull, 0ull, 0ull};
#pragma unroll 8
    for (int k = 0; k < 128; k++) {
        u64 hv = pack2(h_s[prow][k]);
        float4 wa = *(const float4*)&wp[k * 64 + cg * 8];
        float4 wb = *(const float4*)&wp[k * 64 + cg * 8 + 4];
        pacc[0] = fma2(hv, *(const u64*)&wa.x, pacc[0]);
        pacc[1] = fma2(hv, *(const u64*)&wa.z, pacc[1]);
        pacc[2] = fma2(hv, *(const u64*)&wb.x, pacc[2]);
        pacc[3] = fma2(hv, *(const u64*)&wb.z, pacc[3]);
    }
    float4 bpa = *(const float4*)(bp + cg * 8);
    float4 bpb = *(const float4*)(bp + cg * 8 + 4);
    float2 q0 = *(float2*)&pacc[0];
    float2 q1 = *(float2*)&pacc[1];
    float2 q2 = *(float2*)&pacc[2];
    float2 q3 = *(float2*)&pacc[3];
    float4 o0 = make_float4(q0.x + bpa.x, q0.y + bpa.y, q1.x + bpa.z, q1.y + bpa.w);
    float4 o1 = make_float4(q2.x + bpb.x, q2.y + bpb.y, q3.x + bpb.z, q3.y + bpb.w);
    *(float4*)(out + (size_t)orow * 64 + cg * 8)     = o0;
    *(float4*)(out + (size_t)orow * 64 + cg * 8 + 4) = o1;
}

// ---------------- launch --------------------------------------------------------
#define GCN_SMEM64  (4 * 128 * 72 * 2 + 16 * 128 * 4)
#define GCN_SMEM128 (4 * 128 * 136 * 2 + 16 * 128 * 4)

extern "C" void kernel_launch(void* const* d_in, const int* in_sizes, int n_in,
                              void* d_out, int out_size)
{
    const float* x_seq = (const float*)d_in[0];
    const int*   ei    = (const int*)  d_in[1];
    const float* ew    = (const float*)d_in[2];
    const float* W0s   = (const float*)d_in[3];
    const float* b0s   = (const float*)d_in[4];
    const float* W0d   = (const float*)d_in[5];
    const float* b0d   = (const float*)d_in[6];
    const float* W1s   = (const float*)d_in[7];
    const float* b1s   = (const float*)d_in[8];
    const float* W1d   = (const float*)d_in[9];
    const float* b1d   = (const float*)d_in[10];
    const float* Wih   = (const float*)d_in[11];
    const float* Whh   = (const float*)d_in[12];
    const float* bih   = (const float*)d_in[13];
    const float* bhh   = (const float*)d_in[14];
    const float* Wp    = (const float*)d_in[15];
    const float* bp    = (const float*)d_in[16];
    float* out = (float*)d_out;

    float *h0, *h1, *gx, *b0v, *b1v;
    __nv_bfloat16 *afh, *afl, *abh, *abl;
    __nv_bfloat16 *w0sh, *w0sl, *w0dh, *w0dl, *w1sh, *w1sl, *w1dh, *w1dl;
    cudaGetSymbolAddress((void**)&h0,   d_h0);
    cudaGetSymbolAddress((void**)&h1,   d_h1);
    cudaGetSymbolAddress((void**)&gx,   d_gx);
    cudaGetSymbolAddress((void**)&afh,  d_aggfh);
    cudaGetSymbolAddress((void**)&afl,  d_aggfl);
    cudaGetSymbolAddress((void**)&abh,  d_aggbh);
    cudaGetSymbolAddress((void**)&abl,  d_aggbl);
    cudaGetSymbolAddress((void**)&w0sh, d_w0sh);
    cudaGetSymbolAddress((void**)&w0sl, d_w0sl);
    cudaGetSymbolAddress((void**)&w0dh, d_w0dh);
    cudaGetSymbolAddress((void**)&w0dl, d_w0dl);
    cudaGetSymbolAddress((void**)&w1sh, d_w1sh);
    cudaGetSymbolAddress((void**)&w1sl, d_w1sl);
    cudaGetSymbolAddress((void**)&w1dh, d_w1dh);
    cudaGetSymbolAddress((void**)&w1dl, d_w1dl);
    cudaGetSymbolAddress((void**)&b0v,  d_b0v);
    cudaGetSymbolAddress((void**)&b1v,  d_b1v);

    cudaFuncSetAttribute(gx_wmma_kernel,
                         cudaFuncAttributeMaxDynamicSharedMemorySize, GX_SMEM);
    cudaFuncSetAttribute(gcn_wmma_kernel<64>,
                         cudaFuncAttributeMaxDynamicSharedMemorySize, GCN_SMEM64);
    cudaFuncSetAttribute(gcn_wmma_kernel<128>,
                         cudaFuncAttributeMaxDynamicSharedMemorySize, GCN_SMEM128);

    const int M = Gn * NN;   // 128000

    // ---- CSR build + weight prep ----
    zero_kernel<<<(Gn * NN + 255) / 256, 256>>>();
    degcnt_kernel<<<(Gn * EE + 255) / 256, 256>>>(ei, ew);
    inv_kernel<<<(Gn * NN + 255) / 256, 256>>>();
    scan_kernel<<<dim3(Gn, 2), 1024>>>();
    scatter_kernel<<<(Gn * EE + 255) / 256, 256>>>(ei, ew);
    prep_kernel<<<256, 256>>>(Whh, Wp, Wih, bih, bhh,
                              W0s, W0d, W1s, W1d, b0s, b0d, b1s, b1d);

    const int gblocks = (Gn * NN * 2 * 32 + 255) / 256;

    // ---- GCN layer 0 (F=64 -> H=128): gather bf16 + WMMA dual GEMM ----
    gather_kernel<64><<<gblocks, 256>>>(x_seq);
    gcn_wmma_kernel<64><<<M / 128, 256, GCN_SMEM64>>>(
        afh, afl, abh, abl, w0sh, w0sl, w0dh, w0dl, b0v, h0);

    // ---- GCN layer 1 (H=128 -> H=128) ----
    gather_kernel<128><<<gblocks, 256>>>(h0);
    gcn_wmma_kernel<128><<<M / 128, 256, GCN_SMEM128>>>(
        afh, afl, abh, abl, w1sh, w1sl, w1dh, w1dl, b1v, h1);

    // ---- LSTM input GEMM via WMMA bf16x3 ----
    conv_kernel<<<(int)(((size_t)Gn * NN * HD / 4 + 255) / 256), 256>>>();
    gx_wmma_kernel<<<M / 128, 256, GX_SMEM>>>(gx);

    // ---- LSTM recurrence + fused projection ----
    lstm_kernel<<<BNR / 32, 256>>>(out, bp);
}

// round 13
// speedup vs baseline: 1.6674x; 1.0158x over previous
#include <cuda_runtime.h>
#include <cuda_bf16.h>
#include <mma.h>

using namespace nvcuda;

// Problem dims (fixed by the reference)
#define Gn   32
#define NN   4000
#define EE   32000
#define FD0  64
#define HD   128
#define BNR  16000
#define STEPS 8

typedef unsigned long long u64;

__device__ __forceinline__ u64 fma2(u64 a, u64 b, u64 c) {
    u64 d;
    asm("fma.rn.f32x2 %0, %1, %2, %3;" : "=l"(d) : "l"(a), "l"(b), "l"(c));
    return d;
}
__device__ __forceinline__ u64 pack2(float x) {
    u64 d; asm("mov.b64 %0, {%1, %1};" : "=l"(d) : "f"(x)); return d;
}
__device__ __forceinline__ void split_bf16(float v, __nv_bfloat16& hi, __nv_bfloat16& lo) {
    hi = __float2bfloat16(v);
    lo = __float2bfloat16(v - __bfloat162float(hi));
}

// ---------------- scratch (device globals) --------------------------------------
__device__ float d_deg_out[Gn * NN];
__device__ float d_deg_in [Gn * NN];
__device__ int   d_cnt_f[Gn * NN];
__device__ int   d_cnt_b[Gn * NN];
__device__ int   d_off_f[Gn * NN];
__device__ int   d_off_b[Gn * NN];
__device__ int   d_cur_f[Gn * NN];
__device__ int   d_cur_b[Gn * NN];
__device__ int   d_csr_if[Gn * EE];
__device__ float d_csr_wf[Gn * EE];
__device__ int   d_csr_ib[Gn * EE];
__device__ float d_csr_wb[Gn * EE];
// aggregation outputs, bf16 hi/lo
__device__ __nv_bfloat16 d_aggfh[(size_t)Gn * NN * HD];
__device__ __nv_bfloat16 d_aggfl[(size_t)Gn * NN * HD];
__device__ __nv_bfloat16 d_aggbh[(size_t)Gn * NN * HD];
__device__ __nv_bfloat16 d_aggbl[(size_t)Gn * NN * HD];
__device__ float d_h0    [(size_t)Gn * NN * HD];
__device__ float d_gx    [(size_t)BNR * STEPS * 4 * HD];
__device__ float d_whhT  [HD * 4 * HD];   // Whh^T [128][512]
__device__ float d_wpT   [HD * FD0];      // Wp^T  [128][64]
// bf16x3 weight/input images
__device__ __nv_bfloat16 d_h1hi[(size_t)Gn * NN * HD];
__device__ __nv_bfloat16 d_h1lo[(size_t)Gn * NN * HD];
__device__ __nv_bfloat16 d_wihhi[512 * 128];
__device__ __nv_bfloat16 d_wihlo[512 * 128];
__device__ float d_bsum[512];             // bih + bhh
__device__ __nv_bfloat16 d_w0sh[HD * FD0], d_w0sl[HD * FD0];   // 0.5*W0s hi/lo
__device__ __nv_bfloat16 d_w0dh[HD * FD0], d_w0dl[HD * FD0];
__device__ __nv_bfloat16 d_w1sh[HD * HD],  d_w1sl[HD * HD];
__device__ __nv_bfloat16 d_w1dh[HD * HD],  d_w1dl[HD * HD];
__device__ float d_b0v[HD];               // 0.5*(b0s+b0d)
__device__ float d_b1v[HD];

// ---------------- CSR build ------------------------------------------------------
__global__ void zero_kernel() {
    int i = blockIdx.x * blockDim.x + threadIdx.x;
    if (i < Gn * NN) {
        d_deg_out[i] = 0.f; d_deg_in[i] = 0.f;
        d_cnt_f[i] = 0;     d_cnt_b[i] = 0;
    }
}

__global__ void degcnt_kernel(const int* __restrict__ ei, const float* __restrict__ ew) {
    int i = blockIdx.x * blockDim.x + threadIdx.x;
    if (i >= Gn * EE) return;
    int g = i / EE, e = i - g * EE;
    const int* eig = ei + (size_t)g * 2 * EE;
    int src = eig[e], dst = eig[EE + e];
    float w = ew[i];
    atomicAdd(&d_deg_out[g * NN + src], w);
    atomicAdd(&d_deg_in [g * NN + dst], w);
    atomicAdd(&d_cnt_f[g * NN + dst], 1);
    atomicAdd(&d_cnt_b[g * NN + src], 1);
}

__global__ void inv_kernel() {
    int i = blockIdx.x * blockDim.x + threadIdx.x;
    if (i >= Gn * NN) return;
    float v = d_deg_out[i];
    d_deg_out[i] = (v > 0.f) ? rsqrtf(fmaxf(v, 1e-12f)) : 0.f;
    v = d_deg_in[i];
    d_deg_in[i]  = (v > 0.f) ? rsqrtf(fmaxf(v, 1e-12f)) : 0.f;
}

__global__ void __launch_bounds__(1024) scan_kernel() {
    int g   = blockIdx.x;
    int dir = blockIdx.y;
    const int* cnt = dir ? d_cnt_b : d_cnt_f;
    int* off = dir ? d_off_b : d_off_f;
    int* cur = dir ? d_cur_b : d_cur_f;
    int tid = threadIdx.x;
    int base = g * NN;
    int v[4], tot = 0;
#pragma unroll
    for (int k = 0; k < 4; k++) {
        int i = tid * 4 + k;
        v[k] = (i < NN) ? cnt[base + i] : 0;
        tot += v[k];
    }
    __shared__ int s[1024];
    s[tid] = tot;
    __syncthreads();
    for (int d = 1; d < 1024; d <<= 1) {
        int t = (tid >= d) ? s[tid - d] : 0;
        __syncthreads();
        s[tid] += t;
        __syncthreads();
    }
    int ex = s[tid] - tot;
#pragma unroll
    for (int k = 0; k < 4; k++) {
        int i = tid * 4 + k;
        if (i < NN) { off[base + i] = ex; cur[base + i] = ex; ex += v[k]; }
    }
}

__global__ void scatter_kernel(const int* __restrict__ ei, const float* __restrict__ ew) {
    int i = blockIdx.x * blockDim.x + threadIdx.x;
    if (i >= Gn * EE) return;
    int g = i / EE, e = i - g * EE;
    const int* eig = ei + (size_t)g * 2 * EE;
    int src = eig[e], dst = eig[EE + e];
    float w = ew[i] * d_deg_out[g * NN + src] * d_deg_in[g * NN + dst];
    int pf = atomicAdd(&d_cur_f[g * NN + dst], 1);
    d_csr_if[g * EE + pf] = src;
    d_csr_wf[g * EE + pf] = w;
    int pb = atomicAdd(&d_cur_b[g * NN + src], 1);
    d_csr_ib[g * EE + pb] = dst;
    d_csr_wb[g * EE + pb] = w;
}

// ---------------- gather aggregation: one warp per (node, dir), MLP-4 unroll -----
template<int FD>
__global__ void __launch_bounds__(256) gather_kernel(const float* __restrict__ x) {
    int gw = (blockIdx.x * 256 + threadIdx.x) >> 5;
    int lane = threadIdx.x & 31;
    if (gw >= Gn * NN * 2) return;
    int dir = gw & 1;
    int gn  = gw >> 1;
    int g   = gn / NN;
    const int*   off = dir ? d_off_b : d_off_f;
    const int*   cnt = dir ? d_cnt_b : d_cnt_f;
    const int*   nb  = dir ? d_csr_ib : d_csr_if;
    const float* wv  = dir ? d_csr_wb : d_csr_wf;
    __nv_bfloat16* oh = dir ? d_aggbh : d_aggfh;
    __nv_bfloat16* ol = dir ? d_aggbl : d_aggfl;
    int o = off[gn], c = cnt[gn];
    const float* xg = x + (size_t)g * NN * FD;
    const int ebase = g * EE + o;

    if (FD == 128) {
        float4 acc = make_float4(0.f, 0.f, 0.f, 0.f);
        int j = 0;
        for (; j + 4 <= c; j += 4) {
            int   s0 = nb[ebase + j],     s1 = nb[ebase + j + 1];
            int   s2 = nb[ebase + j + 2], s3 = nb[ebase + j + 3];
            float w0 = wv[ebase + j],     w1 = wv[ebase + j + 1];
            float w2 = wv[ebase + j + 2], w3 = wv[ebase + j + 3];
            float4 x0 = *(const float4*)(xg + (size_t)s0 * FD + lane * 4);
            float4 x1 = *(const float4*)(xg + (size_t)s1 * FD + lane * 4);
            float4 x2 = *(const float4*)(xg + (size_t)s2 * FD + lane * 4);
            float4 x3 = *(const float4*)(xg + (size_t)s3 * FD + lane * 4);
            acc.x += w0 * x0.x; acc.y += w0 * x0.y; acc.z += w0 * x0.z; acc.w += w0 * x0.w;
            acc.x += w1 * x1.x; acc.y += w1 * x1.y; acc.z += w1 * x1.z; acc.w += w1 * x1.w;
            acc.x += w2 * x2.x; acc.y += w2 * x2.y; acc.z += w2 * x2.z; acc.w += w2 * x2.w;
            acc.x += w3 * x3.x; acc.y += w3 * x3.y; acc.z += w3 * x3.z; acc.w += w3 * x3.w;
        }
        for (; j < c; j++) {
            int   s = nb[ebase + j];
            float w = wv[ebase + j];
            float4 xv = *(const float4*)(xg + (size_t)s * FD + lane * 4);
            acc.x += w * xv.x; acc.y += w * xv.y;
            acc.z += w * xv.z; acc.w += w * xv.w;
        }
        __nv_bfloat16 hx, lx, hy, ly, hz, lz, hw, lw;
        split_bf16(acc.x, hx, lx); split_bf16(acc.y, hy, ly);
        split_bf16(acc.z, hz, lz); split_bf16(acc.w, hw, lw);
        size_t p = (size_t)gn * FD + lane * 4;
        *(__nv_bfloat162*)(oh + p)     = __nv_bfloat162(hx, hy);
        *(__nv_bfloat162*)(oh + p + 2) = __nv_bfloat162(hz, hw);
        *(__nv_bfloat162*)(ol + p)     = __nv_bfloat162(lx, ly);
        *(__nv_bfloat162*)(ol + p + 2) = __nv_bfloat162(lz, lw);
    } else {
        float2 acc = make_float2(0.f, 0.f);
        int j = 0;
        for (; j + 4 <= c; j += 4) {
            int   s0 = nb[ebase + j],     s1 = nb[ebase + j + 1];
            int   s2 = nb[ebase + j + 2], s3 = nb[ebase + j + 3];
            float w0 = wv[ebase + j],     w1 = wv[ebase + j + 1];
            float w2 = wv[ebase + j + 2], w3 = wv[ebase + j + 3];
            float2 x0 = *(const float2*)(xg + (size_t)s0 * FD + lane * 2);
            float2 x1 = *(const float2*)(xg + (size_t)s1 * FD + lane * 2);
            float2 x2 = *(const float2*)(xg + (size_t)s2 * FD + lane * 2);
            float2 x3 = *(const float2*)(xg + (size_t)s3 * FD + lane * 2);
            acc.x += w0 * x0.x; acc.y += w0 * x0.y;
            acc.x += w1 * x1.x; acc.y += w1 * x1.y;
            acc.x += w2 * x2.x; acc.y += w2 * x2.y;
            acc.x += w3 * x3.x; acc.y += w3 * x3.y;
        }
        for (; j < c; j++) {
            int   s = nb[ebase + j];
            float w = wv[ebase + j];
            float2 xv = *(const float2*)(xg + (size_t)s * FD + lane * 2);
            acc.x += w * xv.x; acc.y += w * xv.y;
        }
        __nv_bfloat16 hx, lx, hy, ly;
        split_bf16(acc.x, hx, lx); split_bf16(acc.y, hy, ly);
        size_t p = (size_t)gn * FD + lane * 2;
        *(__nv_bfloat162*)(oh + p) = __nv_bfloat162(hx, hy);
        *(__nv_bfloat162*)(ol + p) = __nv_bfloat162(lx, ly);
    }
}

// ---------------- GCN dual GEMM via WMMA bf16x3 ----------------------------------
// C = sum_dir Adir @ Wdir^T + bias. SPLIT_OUT=true writes bf16 hi/lo (for h1),
// else fp32. 8 warps: 4x2 of 32x64 subtiles. Grid 1000 blocks.
template<int KD, bool SPLIT_OUT>
__global__ void __launch_bounds__(256)
gcn_wmma_kernel(const __nv_bfloat16* __restrict__ A0h, const __nv_bfloat16* __restrict__ A0l,
                const __nv_bfloat16* __restrict__ A1h, const __nv_bfloat16* __restrict__ A1l,
                const __nv_bfloat16* __restrict__ W0h, const __nv_bfloat16* __restrict__ W0l,
                const __nv_bfloat16* __restrict__ W1h, const __nv_bfloat16* __restrict__ W1l,
                const float* __restrict__ bias, float* __restrict__ C,
                __nv_bfloat16* __restrict__ Chi, __nv_bfloat16* __restrict__ Clo)
{
    constexpr int LD = KD + 8;
    extern __shared__ char smem[];
    __nv_bfloat16* AH = (__nv_bfloat16*)smem;
    __nv_bfloat16* AL = AH + 128 * LD;
    __nv_bfloat16* BH = AL + 128 * LD;
    __nv_bfloat16* BL = BH + 128 * LD;
    float*         BI = (float*)(BL + 128 * LD);

    const int tid = threadIdx.x;
    const int wid = tid >> 5;
    const int m0  = blockIdx.x * 128;
    const int m_off = (wid >> 1) * 32;
    const int n_off = (wid & 1) * 64;
    constexpr int CPR = KD / 8;          // 16B chunks per row

#pragma unroll
    for (int t = 0; t < 8; t++) {
        int i = tid + t * 256;
        BI[i] = bias[i & 127];
    }

    wmma::fragment<wmma::accumulator, 16, 16, 16, float> acc[2][4];

    for (int dir = 0; dir < 2; dir++) {
        const __nv_bfloat16* Ah = dir ? A1h : A0h;
        const __nv_bfloat16* Al = dir ? A1l : A0l;
        const __nv_bfloat16* Wh = dir ? W1h : W0h;
        const __nv_bfloat16* Wl = dir ? W1l : W0l;
        if (dir) __syncthreads();
#pragma unroll
        for (int t = 0; t < KD / 16; t++) {
            int ch = tid + t * 256;
            int r  = ch / CPR;
            int c8 = ch % CPR;
            *(uint4*)(AH + r * LD + c8 * 8) = *(const uint4*)(Ah + (size_t)(m0 + r) * KD + c8 * 8);
            *(uint4*)(AL + r * LD + c8 * 8) = *(const uint4*)(Al + (size_t)(m0 + r) * KD + c8 * 8);
            *(uint4*)(BH + r * LD + c8 * 8) = *(const uint4*)(Wh + (size_t)r * KD + c8 * 8);
            *(uint4*)(BL + r * LD + c8 * 8) = *(const uint4*)(Wl + (size_t)r * KD + c8 * 8);
        }
        __syncthreads();

        if (dir == 0) {
#pragma unroll
            for (int mt = 0; mt < 2; mt++)
#pragma unroll
                for (int nt = 0; nt < 4; nt++)
                    wmma::load_matrix_sync(acc[mt][nt], BI + n_off + nt * 16, 128,
                                           wmma::mem_row_major);
        }

#pragma unroll
        for (int ks = 0; ks < KD / 16; ks++) {
            const int k0 = ks * 16;
            wmma::fragment<wmma::matrix_a, 16, 16, 16, __nv_bfloat16, wmma::row_major> ah[2], al[2];
            wmma::fragment<wmma::matrix_b, 16, 16, 16, __nv_bfloat16, wmma::col_major> bh[4], bl[4];
#pragma unroll
            for (int mt = 0; mt < 2; mt++) {
                wmma::load_matrix_sync(ah[mt], AH + (m_off + mt * 16) * LD + k0, LD);
                wmma::load_matrix_sync(al[mt], AL + (m_off + mt * 16) * LD + k0, LD);
            }
#pragma unroll
            for (int nt = 0; nt < 4; nt++) {
                wmma::load_matrix_sync(bh[nt], BH + (n_off + nt * 16) * LD + k0, LD);
                wmma::load_matrix_sync(bl[nt], BL + (n_off + nt * 16) * LD + k0, LD);
            }
#pragma unroll
            for (int mt = 0; mt < 2; mt++)
#pragma unroll
                for (int nt = 0; nt < 4; nt++) {
                    wmma::mma_sync(acc[mt][nt], ah[mt], bh[nt], acc[mt][nt]);
                    wmma::mma_sync(acc[mt][nt], ah[mt], bl[nt], acc[mt][nt]);
                    wmma::mma_sync(acc[mt][nt], al[mt], bh[nt], acc[mt][nt]);
                }
        }
    }

    if (!SPLIT_OUT) {
#pragma unroll
        for (int mt = 0; mt < 2; mt++)
#pragma unroll
            for (int nt = 0; nt < 4; nt++)
                wmma::store_matrix_sync(
                    C + (size_t)(m0 + m_off + mt * 16) * 128 + n_off + nt * 16,
                    acc[mt][nt], 128, wmma::mem_row_major);
    } else {
        // stage result in smem (fp32 128x128 = 64 KB fits in the bf16 tile areas)
        float* SF = (float*)smem;
        __syncthreads();   // done reading AH..BL
#pragma unroll
        for (int mt = 0; mt < 2; mt++)
#pragma unroll
            for (int nt = 0; nt < 4; nt++)
                wmma::store_matrix_sync(
                    SF + (m_off + mt * 16) * 128 + n_off + nt * 16,
                    acc[mt][nt], 128, wmma::mem_row_major);
        __syncthreads();
#pragma unroll
        for (int t = 0; t < 32; t++) {   // FIX: 8192 float2 chunks = 32 * 256
            int i = tid + t * 256;
            float2 v = *(const float2*)(SF + i * 2);
            __nv_bfloat16 hx, lx, hy, ly;
            split_bf16(v.x, hx, lx); split_bf16(v.y, hy, ly);
            int r = i >> 6, cc = (i & 63) * 2;
            size_t p = (size_t)(m0 + r) * 128 + cc;
            *(__nv_bfloat162*)(Chi + p) = __nv_bfloat162(hx, hy);
            *(__nv_bfloat162*)(Clo + p) = __nv_bfloat162(lx, ly);
        }
    }
}

// ---------------- prep: all weight images + bias sums ----------------------------
__global__ void prep_kernel(const float* __restrict__ Whh, const float* __restrict__ Wp,
                            const float* __restrict__ Wih, const float* __restrict__ bih,
                            const float* __restrict__ bhh,
                            const float* __restrict__ W0s, const float* __restrict__ W0d,
                            const float* __restrict__ W1s, const float* __restrict__ W1d,
                            const float* __restrict__ b0s, const float* __restrict__ b0d,
                            const float* __restrict__ b1s, const float* __restrict__ b1d) {
    int i = blockIdx.x * blockDim.x + threadIdx.x;
    if (i < 512 * 128) {
        int j = i >> 7, k = i & 127;
        d_whhT[(size_t)k * 512 + j] = Whh[i];
        split_bf16(Wih[i], d_wihhi[i], d_wihlo[i]);
    }
    if (i < 128 * 64) {
        split_bf16(0.5f * W0s[i], d_w0sh[i], d_w0sl[i]);
        split_bf16(0.5f * W0d[i], d_w0dh[i], d_w0dl[i]);
    }
    if (i < 128 * 128) {
        split_bf16(0.5f * W1s[i], d_w1sh[i], d_w1sl[i]);
        split_bf16(0.5f * W1d[i], d_w1dh[i], d_w1dl[i]);
    }
    if (i < 64 * 128) {
        int j = i >> 7, k = i & 127;
        d_wpT[k * 64 + j] = Wp[i];
    }
    if (i < 512) d_bsum[i] = bih[i] + bhh[i];
    if (i < 128) {
        d_b0v[i] = 0.5f * (b0s[i] + b0d[i]);
        d_b1v[i] = 0.5f * (b1s[i] + b1d[i]);
    }
}

// ---------------- gx GEMM via WMMA bf16x3 (round-10 winner, unchanged) -----------
#define LDAB 136
#define SM_AH 0
#define SM_AL (128 * LDAB * 2)
#define SM_BH (2 * 128 * LDAB * 2)
#define SM_BL (3 * 128 * LDAB * 2)
#define SM_BI (4 * 128 * LDAB * 2)
#define GX_SMEM (4 * 128 * LDAB * 2 + 16 * 128 * 4)

__global__ void __launch_bounds__(256)
gx_wmma_kernel(float* __restrict__ gx)
{
    extern __shared__ char smem[];
    __nv_bfloat16* AH = (__nv_bfloat16*)(smem + SM_AH);
    __nv_bfloat16* AL = (__nv_bfloat16*)(smem + SM_AL);
    __nv_bfloat16* BH = (__nv_bfloat16*)(smem + SM_BH);
    __nv_bfloat16* BL = (__nv_bfloat16*)(smem + SM_BL);
    float*         BI = (float*)(smem + SM_BI);

    const int tid = threadIdx.x;
    const int wid = tid >> 5;
    const int m0  = blockIdx.x * 128;
    const int m_off = (wid >> 1) * 32;
    const int n_off = (wid & 1) * 64;

#pragma unroll
    for (int t = 0; t < 8; t++) {
        int ch = tid + t * 256;
        int r  = ch >> 4;
        int c16 = ch & 15;
        size_t gsrc = (size_t)(m0 + r) * 128 + c16 * 8;
        *(uint4*)(AH + r * LDAB + c16 * 8) = *(const uint4*)(d_h1hi + gsrc);
        *(uint4*)(AL + r * LDAB + c16 * 8) = *(const uint4*)(d_h1lo + gsrc);
    }

    for (int q = 0; q < 4; q++) {
        __syncthreads();
#pragma unroll
        for (int t = 0; t < 8; t++) {
            int ch = tid + t * 256;
            int r  = ch >> 4;
            int c16 = ch & 15;
            size_t gsrc = (size_t)(q * 128 + r) * 128 + c16 * 8;
            *(uint4*)(BH + r * LDAB + c16 * 8) = *(const uint4*)(d_wihhi + gsrc);
            *(uint4*)(BL + r * LDAB + c16 * 8) = *(const uint4*)(d_wihlo + gsrc);
        }
#pragma unroll
        for (int t = 0; t < 8; t++) {
            int i = tid + t * 256;
            BI[i] = d_bsum[q * 128 + (i & 127)];
        }
        __syncthreads();

        wmma::fragment<wmma::accumulator, 16, 16, 16, float> acc[2][4];
#pragma unroll
        for (int mt = 0; mt < 2; mt++)
#pragma unroll
            for (int nt = 0; nt < 4; nt++)
                wmma::load_matrix_sync(acc[mt][nt], BI + n_off + nt * 16, 128,
                                       wmma::mem_row_major);

#pragma unroll
        for (int ks = 0; ks < 8; ks++) {
            const int k0 = ks * 16;
            wmma::fragment<wmma::matrix_a, 16, 16, 16, __nv_bfloat16, wmma::row_major> ah[2], al[2];
            wmma::fragment<wmma::matrix_b, 16, 16, 16, __nv_bfloat16, wmma::col_major> bh[4], bl[4];
#pragma unroll
            for (int mt = 0; mt < 2; mt++) {
                wmma::load_matrix_sync(ah[mt], AH + (m_off + mt * 16) * LDAB + k0, LDAB);
                wmma::load_matrix_sync(al[mt], AL + (m_off + mt * 16) * LDAB + k0, LDAB);
            }
#pragma unroll
            for (int nt = 0; nt < 4; nt++) {
                wmma::load_matrix_sync(bh[nt], BH + (n_off + nt * 16) * LDAB + k0, LDAB);
                wmma::load_matrix_sync(bl[nt], BL + (n_off + nt * 16) * LDAB + k0, LDAB);
            }
#pragma unroll
            for (int mt = 0; mt < 2; mt++)
#pragma unroll
                for (int nt = 0; nt < 4; nt++) {
                    wmma::mma_sync(acc[mt][nt], ah[mt], bh[nt], acc[mt][nt]);
                    wmma::mma_sync(acc[mt][nt], ah[mt], bl[nt], acc[mt][nt]);
                    wmma::mma_sync(acc[mt][nt], al[mt], bh[nt], acc[mt][nt]);
                }
        }

#pragma unroll
        for (int mt = 0; mt < 2; mt++)
#pragma unroll
            for (int nt = 0; nt < 4; nt++)
                wmma::store_matrix_sync(
                    gx + (size_t)(m0 + m_off + mt * 16) * 512 + q * 128 + n_off + nt * 16,
                    acc[mt][nt], 512, wmma::mem_row_major);
    }
}

// ---------------- LSTM recurrence + fused projection (unchanged) -----------------
__device__ __forceinline__ float sigmoidf_(float x) { return 1.f / (1.f + __expf(-x)); }

__global__ void __launch_bounds__(256)
lstm_kernel(float* __restrict__ out, const float* __restrict__ bp)
{
    __shared__ float h_s[32][128];
    __shared__ float w_s[16][512];
    const int tid  = threadIdx.x;
    const int tc   = tid & 31;
    const int tr   = tid >> 5;
    const int row0 = blockIdx.x * 32 + tr * 4;

    float c[4][4];
#pragma unroll
    for (int a = 0; a < 4; a++)
#pragma unroll
        for (int b = 0; b < 4; b++) c[a][b] = 0.f;

    for (int t = 0; t < STEPS; t++) {
        u64 acc[4][4][2];
#pragma unroll
        for (int gate = 0; gate < 4; gate++)
#pragma unroll
            for (int ri = 0; ri < 4; ri++) {
                float4 v = *(const float4*)(d_gx +
                    ((size_t)(row0 + ri) * STEPS + t) * 512 + gate * 128 + tc * 4);
                acc[gate][ri][0] = *(const u64*)&v.x;
                acc[gate][ri][1] = *(const u64*)&v.z;
            }

        if (t > 0) {
            for (int kt = 0; kt < 8; kt++) {
                __syncthreads();
#pragma unroll
                for (int i = 0; i < 8; i++) {
                    int q  = tid + i * 256;
                    int kk = q >> 7;
                    int j4 = (q & 127) << 2;
                    *(float4*)&w_s[kk][j4] =
                        *(const float4*)(d_whhT + (size_t)(kt * 16 + kk) * 512 + j4);
                }
                __syncthreads();
#pragma unroll
                for (int kk = 0; kk < 16; kk++) {
                    u64 hp[4];
#pragma unroll
                    for (int ri = 0; ri < 4; ri++)
                        hp[ri] = pack2(h_s[tr * 4 + ri][kt * 16 + kk]);
#pragma unroll
                    for (int gate = 0; gate < 4; gate++) {
                        float4 w = *(const float4*)&w_s[kk][gate * 128 + tc * 4];
                        u64 w01 = *(const u64*)&w.x;
                        u64 w23 = *(const u64*)&w.z;
#pragma unroll
                        for (int ri = 0; ri < 4; ri++) {
                            acc[gate][ri][0] = fma2(hp[ri], w01, acc[gate][ri][0]);
                            acc[gate][ri][1] = fma2(hp[ri], w23, acc[gate][ri][1]);
                        }
                    }
                }
            }
            __syncthreads();
        }

#pragma unroll
        for (int ri = 0; ri < 4; ri++) {
            float2 i01 = *(float2*)&acc[0][ri][0], i23 = *(float2*)&acc[0][ri][1];
            float2 f01 = *(float2*)&acc[1][ri][0], f23 = *(float2*)&acc[1][ri][1];
            float2 g01 = *(float2*)&acc[2][ri][0], g23 = *(float2*)&acc[2][ri][1];
            float2 o01 = *(float2*)&acc[3][ri][0], o23 = *(float2*)&acc[3][ri][1];
            float ig[4] = {i01.x, i01.y, i23.x, i23.y};
            float fg[4] = {f01.x, f01.y, f23.x, f23.y};
            float gg[4] = {g01.x, g01.y, g23.x, g23.y};
            float og[4] = {o01.x, o01.y, o23.x, o23.y};
            float hn[4];
#pragma unroll
            for (int ci = 0; ci < 4; ci++) {
                float iv = sigmoidf_(ig[ci]);
                float fv = sigmoidf_(fg[ci]);
                float gv = tanhf(gg[ci]);
                float ov = sigmoidf_(og[ci]);
                float cn = fv * c[ri][ci] + iv * gv;
                c[ri][ci] = cn;
                hn[ci] = ov * tanhf(cn);
            }
            *(float4*)&h_s[tr * 4 + ri][tc * 4] = make_float4(hn[0], hn[1], hn[2], hn[3]);
        }
        __syncthreads();
    }

    float* wp = &w_s[0][0];
#pragma unroll
    for (int i = 0; i < 8; i++) {
        int q = tid + i * 256;
        *(float4*)&wp[q * 4] = *(const float4*)(d_wpT + q * 4);
    }
    __syncthreads();

    const int prow = tid >> 3;
    const int cg   = tid & 7;
    const int orow = blockIdx.x * 32 + prow;
    u64 pacc[4] = {0ull, 0ull, 0ull, 0ull};
#pragma unroll 8
    for (int k = 0; k < 128; k++) {
        u64 hv = pack2(h_s[prow][k]);
        float4 wa = *(const float4*)&wp[k * 64 + cg * 8];
        float4 wb = *(const float4*)&wp[k * 64 + cg * 8 + 4];
        pacc[0] = fma2(hv, *(const u64*)&wa.x, pacc[0]);
        pacc[1] = fma2(hv, *(const u64*)&wa.z, pacc[1]);
        pacc[2] = fma2(hv, *(const u64*)&wb.x, pacc[2]);
        pacc[3] = fma2(hv, *(const u64*)&wb.z, pacc[3]);
    }
    float4 bpa = *(const float4*)(bp + cg * 8);
    float4 bpb = *(const float4*)(bp + cg * 8 + 4);
    float2 q0 = *(float2*)&pacc[0];
    float2 q1 = *(float2*)&pacc[1];
    float2 q2 = *(float2*)&pacc[2];
    float2 q3 = *(float2*)&pacc[3];
    float4 o0 = make_float4(q0.x + bpa.x, q0.y + bpa.y, q1.x + bpa.z, q1.y + bpa.w);
    float4 o1 = make_float4(q2.x + bpb.x, q2.y + bpb.y, q3.x + bpb.z, q3.y + bpb.w);
    *(float4*)(out + (size_t)orow * 64 + cg * 8)     = o0;
    *(float4*)(out + (size_t)orow * 64 + cg * 8 + 4) = o1;
}

// ---------------- launch --------------------------------------------------------
#define GCN_SMEM64  (4 * 128 * 72 * 2 + 16 * 128 * 4)
#define GCN_SMEM128 (4 * 128 * 136 * 2 + 16 * 128 * 4)

extern "C" void kernel_launch(void* const* d_in, const int* in_sizes, int n_in,
                              void* d_out, int out_size)
{
    const float* x_seq = (const float*)d_in[0];
    const int*   ei    = (const int*)  d_in[1];
    const float* ew    = (const float*)d_in[2];
    const float* W0s   = (const float*)d_in[3];
    const float* b0s   = (const float*)d_in[4];
    const float* W0d   = (const float*)d_in[5];
    const float* b0d   = (const float*)d_in[6];
    const float* W1s   = (const float*)d_in[7];
    const float* b1s   = (const float*)d_in[8];
    const float* W1d   = (const float*)d_in[9];
    const float* b1d   = (const float*)d_in[10];
    const float* Wih   = (const float*)d_in[11];
    const float* Whh   = (const float*)d_in[12];
    const float* bih   = (const float*)d_in[13];
    const float* bhh   = (const float*)d_in[14];
    const float* Wp    = (const float*)d_in[15];
    const float* bp    = (const float*)d_in[16];
    float* out = (float*)d_out;

    float *h0, *gx, *b0v, *b1v;
    __nv_bfloat16 *afh, *afl, *abh, *abl, *h1hi, *h1lo;
    __nv_bfloat16 *w0sh, *w0sl, *w0dh, *w0dl, *w1sh, *w1sl, *w1dh, *w1dl;
    cudaGetSymbolAddress((void**)&h0,   d_h0);
    cudaGetSymbolAddress((void**)&gx,   d_gx);
    cudaGetSymbolAddress((void**)&afh,  d_aggfh);
    cudaGetSymbolAddress((void**)&afl,  d_aggfl);
    cudaGetSymbolAddress((void**)&abh,  d_aggbh);
    cudaGetSymbolAddress((void**)&abl,  d_aggbl);
    cudaGetSymbolAddress((void**)&h1hi, d_h1hi);
    cudaGetSymbolAddress((void**)&h1lo, d_h1lo);
    cudaGetSymbolAddress((void**)&w0sh, d_w0sh);
    cudaGetSymbolAddress((void**)&w0sl, d_w0sl);
    cudaGetSymbolAddress((void**)&w0dh, d_w0dh);
    cudaGetSymbolAddress((void**)&w0dl, d_w0dl);
    cudaGetSymbolAddress((void**)&w1sh, d_w1sh);
    cudaGetSymbolAddress((void**)&w1sl, d_w1sl);
    cudaGetSymbolAddress((void**)&w1dh, d_w1dh);
    cudaGetSymbolAddress((void**)&w1dl, d_w1dl);
    cudaGetSymbolAddress((void**)&b0v,  d_b0v);
    cudaGetSymbolAddress((void**)&b1v,  d_b1v);

    cudaFuncSetAttribute(gx_wmma_kernel,
                         cudaFuncAttributeMaxDynamicSharedMemorySize, GX_SMEM);
    cudaFuncSetAttribute((const void*)gcn_wmma_kernel<64, false>,
                         cudaFuncAttributeMaxDynamicSharedMemorySize, GCN_SMEM64);
    cudaFuncSetAttribute((const void*)gcn_wmma_kernel<128, true>,
                         cudaFuncAttributeMaxDynamicSharedMemorySize, GCN_SMEM128);

    const int M = Gn * NN;   // 128000

    // ---- CSR build + weight prep ----
    zero_kernel<<<(Gn * NN + 255) / 256, 256>>>();
    degcnt_kernel<<<(Gn * EE + 255) / 256, 256>>>(ei, ew);
    inv_kernel<<<(Gn * NN + 255) / 256, 256>>>();
    scan_kernel<<<dim3(Gn, 2), 1024>>>();
    scatter_kernel<<<(Gn * EE + 255) / 256, 256>>>(ei, ew);
    prep_kernel<<<256, 256>>>(Whh, Wp, Wih, bih, bhh,
                              W0s, W0d, W1s, W1d, b0s, b0d, b1s, b1d);

    const int gblocks = (Gn * NN * 2 * 32 + 255) / 256;

    // ---- GCN layer 0 (F=64 -> H=128): gather bf16 + WMMA dual GEMM (fp32 out) ----
    gather_kernel<64><<<gblocks, 256>>>(x_seq);
    gcn_wmma_kernel<64, false><<<M / 128, 256, GCN_SMEM64>>>(
        afh, afl, abh, abl, w0sh, w0sl, w0dh, w0dl, b0v, h0, nullptr, nullptr);

    // ---- GCN layer 1 (H=128 -> H=128): WMMA dual GEMM -> h1 bf16 hi/lo direct ----
    gather_kernel<128><<<gblocks, 256>>>(h0);
    gcn_wmma_kernel<128, true><<<M / 128, 256, GCN_SMEM128>>>(
        afh, afl, abh, abl, w1sh, w1sl, w1dh, w1dl, b1v, nullptr, h1hi, h1lo);

    // ---- LSTM input GEMM via WMMA bf16x3 (conv eliminated) ----
    gx_wmma_kernel<<<M / 128, 256, GX_SMEM>>>(gx);

    // ---- LSTM recurrence + fused projection ----
    lstm_kernel<<<BNR / 32, 256>>>(out, bp);
}